// round 12
// baseline (speedup 1.0000x reference)
#include <cuda_runtime.h>
#include <cuda_fp16.h>
#include <math.h>

#define D_MODEL 1024
#define NHEAD   16
#define DK      64
#define DFF     4096
#define SEQ     2048
#define BATCH   2
#define ROWS    (BATCH*SEQ)
#define EPS     1e-5f
#define HZ      (BATCH*NHEAD)
#define QKV3    3072

// ---------------- scratch (no allocation allowed) ----------------
__device__ __align__(256) float g_t [(size_t)ROWS*D_MODEL];
__device__ __align__(256) float g_h [(size_t)ROWS*D_MODEL];
__device__ __align__(256) float g_attn_f32[(size_t)HZ*SEQ*SEQ];  // fallback only
__device__ __align__(256) float2 g_stats[(size_t)HZ*32*SEQ];
__device__ __align__(256) float2 g_MS[(size_t)HZ*SEQ];
__device__ __align__(256) __half g_xc_h [(size_t)ROWS*D_MODEL];
__device__ __align__(256) __half g_Wqkv_h[(size_t)QKV3*D_MODEL], g_Wqkv_l[(size_t)QKV3*D_MODEL];
__device__ __align__(256) __half g_Wot_h[(size_t)D_MODEL*D_MODEL], g_Wot_l[(size_t)D_MODEL*D_MODEL];
__device__ __align__(256) __half g_W1t_h[(size_t)D_MODEL*DFF],     g_W1t_l[(size_t)D_MODEL*DFF];
__device__ __align__(256) __half g_W2t_h[(size_t)D_MODEL*DFF],     g_W2t_l[(size_t)D_MODEL*DFF];
__device__ __align__(256) __half g_qkv_h[(size_t)ROWS*QKV3], g_qkv_l[(size_t)ROWS*QKV3];
__device__ __align__(256) __half g_Vt_h [(size_t)HZ*DK*SEQ],  g_Vt_l [(size_t)HZ*DK*SEQ];
__device__ __align__(256) __half g_ctx_h[(size_t)ROWS*D_MODEL];
__device__ __align__(256) __half g_hc_h [(size_t)ROWS*D_MODEL];
__device__ __align__(256) __half g_ff_h [(size_t)ROWS*DFF];

// ---------------- helpers ----------------
__device__ __forceinline__ unsigned s2u(const void* p){
    unsigned a;
    asm("{ .reg .u64 t; cvta.to.shared.u64 t, %1; cvt.u32.u64 %0, t; }" : "=r"(a) : "l"(p));
    return a;
}
__device__ __forceinline__ void cpa(unsigned s, const void* g){
    asm volatile("cp.async.cg.shared.global [%0], [%1], 16;" :: "r"(s), "l"(g));
}
__device__ __forceinline__ void ldmx4(unsigned* r, unsigned addr){
    asm volatile("ldmatrix.sync.aligned.m8n8.x4.shared.b16 {%0,%1,%2,%3}, [%4];"
        : "=r"(r[0]), "=r"(r[1]), "=r"(r[2]), "=r"(r[3]) : "r"(addr));
}
__device__ __forceinline__ void mma16816(float* c, const unsigned* a, unsigned b0, unsigned b1){
    asm volatile("mma.sync.aligned.m16n8k16.row.col.f32.f16.f16.f32 "
        "{%0,%1,%2,%3}, {%4,%5,%6,%7}, {%8,%9}, {%0,%1,%2,%3};"
        : "+f"(c[0]), "+f"(c[1]), "+f"(c[2]), "+f"(c[3])
        : "r"(a[0]), "r"(a[1]), "r"(a[2]), "r"(a[3]), "r"(b0), "r"(b1));
}
// fp16-accumulate MMA (2x rate) for the lo term
__device__ __forceinline__ void mma16816h(unsigned* c, const unsigned* a, unsigned b0, unsigned b1){
    asm volatile("mma.sync.aligned.m16n8k16.row.col.f16.f16.f16.f16 "
        "{%0,%1}, {%2,%3,%4,%5}, {%6,%7}, {%0,%1};"
        : "+r"(c[0]), "+r"(c[1])
        : "r"(a[0]), "r"(a[1]), "r"(a[2]), "r"(a[3]), "r"(b0), "r"(b1));
}
__device__ __forceinline__ void split_h(float v0, float v1, __half* hi, __half* lo){
    __half h0 = __float2half_rn(v0), h1 = __float2half_rn(v1);
    *(__half2*)hi = __halves2half2(h0, h1);
    if (lo)
        *(__half2*)lo = __halves2half2(__float2half_rn(v0 - __half2float(h0)),
                                       __float2half_rn(v1 - __half2float(h1)));
}
__device__ __forceinline__ float2 h2f2(unsigned u){
    __half2 h = *(__half2*)&u;
    return __half22float2(h);
}

// ================= 2-term split-fp16 HMMA GEMM =================
// CTA tile 128x64, K-chunk 32, 8 warps, warp tile 32x32, 3-stage cp.async, 1 sync/iter, 3 CTAs/SM.
// hi term -> fp32 acc; lo term -> fp16 acc (2x rate), combined in epilogue.
// EPI: 0 fp32+bias | 2 f16+bias+relu (hi only) | 3 fp32+mask+row-stats | 5 f16split 3-seg bias (QKV)
template<int EPI, int AOFF, int BOFF, int COFF>
__global__ void __launch_bounds__(256, 3) gemm_mm(
    const __half* __restrict__ Ah, int lda, long long sAz,
    const __half* __restrict__ Bh, const __half* __restrict__ Bl, int ldb, long long sBz,
    float* __restrict__ Cf, __half* __restrict__ Chi, __half* __restrict__ Clo,
    long long sCz, int ldc,
    const float* __restrict__ bias, const float* __restrict__ bias2, const float* __restrict__ bias3,
    const int* __restrict__ mask, float2* __restrict__ stats, int K)
{
    constexpr int BN = 64;
    constexpr int NT = 4;
    constexpr int ABYTES = 128 * 80;
    constexpr int BBYTES = BN * 80;
    constexpr int BUFB = ABYTES + 2 * BBYTES;   // 20480
    extern __shared__ __align__(128) char smem[];
    const unsigned sb = s2u(smem);
    const int tid = threadIdx.x;
    const int m0 = blockIdx.y * 128, n0 = blockIdx.x * BN, z = blockIdx.z;

    size_t ao = (AOFF == 1) ? ((size_t)(z >> 4) * SEQ * lda + (size_t)(z & 15) * DK + (size_t)sAz)
                            : (size_t)z * sAz;
    size_t bo = (BOFF == 1) ? ((size_t)(z >> 4) * SEQ * ldb + (size_t)(z & 15) * DK + (size_t)sBz)
                            : (size_t)z * sBz;
    size_t co = (COFF == 1) ? ((size_t)(z >> 4) * SEQ * ldc + (size_t)(z & 15) * DK)
                            : (size_t)z * sCz;

    const int lane = tid & 31, w = tid >> 5;
    const int warp_m = w & 3, warp_n = w >> 2;

    float acc[2][NT][4];
    unsigned accl[2][NT][2];
#pragma unroll
    for (int mt = 0; mt < 2; mt++)
#pragma unroll
        for (int nt = 0; nt < NT; nt++) {
#pragma unroll
            for (int e = 0; e < 4; e++) acc[mt][nt][e] = 0.f;
            accl[mt][nt][0] = 0u; accl[mt][nt][1] = 0u;
        }

    const int nchunk = K >> 5;

    auto load_tile = [&](int c, int buf) {
        unsigned sbuf = sb + buf * BUFB;
        const __half* pah = Ah + ao + (size_t)m0 * lda + c * 32;
#pragma unroll
        for (int i = 0; i < 2; i++) {
            int idx = tid + i * 256;
            int row = idx >> 2, ch = idx & 3;
            cpa(sbuf + row * 80 + ch * 16, pah + (size_t)row * lda + ch * 8);
        }
        const __half* pbh = Bh + bo + (size_t)n0 * ldb + c * 32;
        const __half* pbl = Bl + bo + (size_t)n0 * ldb + c * 32;
        {
            int row = tid >> 2, ch = tid & 3;
            unsigned so = row * 80 + ch * 16;
            cpa(sbuf + ABYTES + so,          pbh + (size_t)row * ldb + ch * 8);
            cpa(sbuf + ABYTES + BBYTES + so, pbl + (size_t)row * ldb + ch * 8);
        }
    };

    auto compute = [&](unsigned sbuf) {
        unsigned sa  = sbuf + (warp_m * 32 + (lane & 15)) * 80 + (lane >> 4) * 16;
        unsigned sbb = sbuf + ABYTES
                     + (warp_n * 32 + (lane & 7) + ((lane >> 4) << 3)) * 80
                     + ((lane >> 3) & 1) * 16;
#pragma unroll
        for (int ks = 0; ks < 2; ks++) {
            unsigned ah[2][4];
            ldmx4(ah[0], sa + ks * 32);
            ldmx4(ah[1], sa + 16 * 80 + ks * 32);
#pragma unroll
            for (int p = 0; p < 2; p++) {
                unsigned bh[4], bl[4];
                ldmx4(bh, sbb + p * 16 * 80 + ks * 32);
                ldmx4(bl, sbb + BBYTES + p * 16 * 80 + ks * 32);
#pragma unroll
                for (int mt = 0; mt < 2; mt++)
#pragma unroll
                    for (int t = 0; t < 2; t++) {
                        mma16816(acc[mt][2 * p + t], ah[mt], bh[2 * t], bh[2 * t + 1]);
                        mma16816h(accl[mt][2 * p + t], ah[mt], bl[2 * t], bl[2 * t + 1]);
                    }
            }
        }
    };

    load_tile(0, 0);
    asm volatile("cp.async.commit_group;");
    if (nchunk > 1) { load_tile(1, 1); asm volatile("cp.async.commit_group;"); }
    for (int c = 0; c < nchunk; c++) {
        if (c + 1 < nchunk) asm volatile("cp.async.wait_group 1;");
        else                asm volatile("cp.async.wait_group 0;");
        __syncthreads();
        if (c + 2 < nchunk) {
            load_tile(c + 2, (c + 2) % 3);
            asm volatile("cp.async.commit_group;");
        }
        compute(sb + (c % 3) * BUFB);
    }

    // fold lo (fp16) accumulators into fp32
#pragma unroll
    for (int mt = 0; mt < 2; mt++)
#pragma unroll
        for (int nt = 0; nt < NT; nt++) {
            float2 l0 = h2f2(accl[mt][nt][0]);
            float2 l1 = h2f2(accl[mt][nt][1]);
            acc[mt][nt][0] += l0.x; acc[mt][nt][1] += l0.y;
            acc[mt][nt][2] += l1.x; acc[mt][nt][3] += l1.y;
        }

    // -------- epilogue --------
    const int g = lane >> 2, q = lane & 3;
    if (EPI == 3) {
        __syncthreads();
        float* stg = (float*)smem;             // 128 x 64, pitch 68
#pragma unroll
        for (int mt = 0; mt < 2; mt++) {
            int sr = warp_m * 32 + mt * 16 + g;
#pragma unroll
            for (int nt = 0; nt < NT; nt++) {
                int sc = warp_n * 32 + nt * 8 + q * 2;
                stg[sr * 68 + sc]           = acc[mt][nt][0];
                stg[sr * 68 + sc + 1]       = acc[mt][nt][1];
                stg[(sr + 8) * 68 + sc]     = acc[mt][nt][2];
                stg[(sr + 8) * 68 + sc + 1] = acc[mt][nt][3];
            }
        }
        __syncthreads();
        const int* mrow = mask + (size_t)(z >> 4) * SEQ;
#pragma unroll
        for (int i = 0; i < 8; i++) {
            int idx = tid + i * 256, row = idx >> 4, c4 = (idx & 15) * 4;
            float4 v;
            v.x = stg[row * 68 + c4];
            v.y = stg[row * 68 + c4 + 1];
            v.z = stg[row * 68 + c4 + 2];
            v.w = stg[row * 68 + c4 + 3];
            int4 mk = *(const int4*)(mrow + n0 + c4);
            v.x = mk.x ? v.x : -1e9f;
            v.y = mk.y ? v.y : -1e9f;
            v.z = mk.z ? v.z : -1e9f;
            v.w = mk.w ? v.w : -1e9f;
            *(float4*)(Cf + co + (size_t)(m0 + row) * ldc + n0 + c4) = v;
        }
        {
            int row = tid >> 1, half = tid & 1;
            float m = -3.4e38f;
#pragma unroll 8
            for (int c2 = 0; c2 < 32; c2++) {
                float xv = stg[row * 68 + half * 32 + c2];
                if (mrow[n0 + half * 32 + c2] == 0) xv = -1e9f;
                m = fmaxf(m, xv);
            }
            float m2 = fmaxf(m, __shfl_xor_sync(0xffffffffu, m, 1));
            float s = 0.f;
#pragma unroll 8
            for (int c2 = 0; c2 < 32; c2++) {
                float xv = stg[row * 68 + half * 32 + c2];
                if (mrow[n0 + half * 32 + c2] == 0) xv = -1e9f;
                s += __expf(xv - m2);
            }
            s += __shfl_xor_sync(0xffffffffu, s, 1);
            if (half == 0)
                stats[((size_t)z * 32 + blockIdx.x) * SEQ + m0 + row] = make_float2(m2, s);
        }
        return;
    }
#pragma unroll
    for (int mt = 0; mt < 2; mt++) {
        int r0 = m0 + warp_m * 32 + mt * 16 + g;
#pragma unroll
        for (int nt = 0; nt < NT; nt++) {
            int col = n0 + warp_n * 32 + nt * 8 + q * 2;
            float c0 = acc[mt][nt][0], c1 = acc[mt][nt][1];
            float c2 = acc[mt][nt][2], c3 = acc[mt][nt][3];
            if (EPI == 0) {
                float b0v = bias[col], b1v = bias[col + 1];
                float2 v0, v1;
                v0.x = c0 + b0v; v0.y = c1 + b1v;
                v1.x = c2 + b0v; v1.y = c3 + b1v;
                *(float2*)(Cf + co + (size_t)r0 * ldc + col)       = v0;
                *(float2*)(Cf + co + (size_t)(r0 + 8) * ldc + col) = v1;
            } else {
                float b0v, b1v;
                if (EPI == 5) {
                    int seg = col >> 10, cc = col & 1023;
                    const float* bp = (seg == 0) ? bias : ((seg == 1) ? bias2 : bias3);
                    float sc = (seg == 0) ? 0.125f : 1.0f;
                    b0v = bp[cc] * sc; b1v = bp[cc + 1] * sc;
                } else {
                    b0v = bias[col]; b1v = bias[col + 1];
                }
                c0 += b0v; c1 += b1v; c2 += b0v; c3 += b1v;
                if (EPI == 2) {
                    c0 = fmaxf(c0, 0.f); c1 = fmaxf(c1, 0.f);
                    c2 = fmaxf(c2, 0.f); c3 = fmaxf(c3, 0.f);
                }
                size_t o0 = co + (size_t)r0 * ldc + col;
                size_t o1 = co + (size_t)(r0 + 8) * ldc + col;
                split_h(c0, c1, Chi + o0, Clo ? Clo + o0 : nullptr);
                split_h(c2, c3, Chi + o1, Clo ? Clo + o1 : nullptr);
            }
        }
    }
}

// ---------------- merge per-tile stats -> per-row (M, 1/S) ----------------
__global__ void __launch_bounds__(256) merge_stats(const float2* __restrict__ stats,
                                                   float2* __restrict__ MS)
{
    int idx = blockIdx.x * 256 + threadIdx.x;
    int z = idx >> 11, r = idx & 2047;
    const float2* sp = stats + (size_t)z * 32 * SEQ + r;
    float M = -3.4e38f;
#pragma unroll
    for (int jt = 0; jt < 32; jt++) M = fmaxf(M, sp[(size_t)jt * SEQ].x);
    float S = 0.f;
#pragma unroll
    for (int jt = 0; jt < 32; jt++) {
        float2 t = sp[(size_t)jt * SEQ];
        S += t.y * __expf(t.x - M);
    }
    MS[(size_t)z * SEQ + r] = make_float2(M, 1.0f / S);
}

// ================= ctx: normalize raw scores in place + 2-term GEMM with Vt =================
__global__ void __launch_bounds__(256, 3) ctx_mm(
    float* __restrict__ attn, const float2* __restrict__ MS,
    const __half* __restrict__ Bh, const __half* __restrict__ Bl,
    __half* __restrict__ Chi)
{
    constexpr int NT = 4;
    constexpr int ABYTES = 128 * 80;
    constexpr int BBYTES = 64 * 80;
    constexpr int BSTG = 2 * BBYTES;
    extern __shared__ __align__(128) char smem[];
    const unsigned sb = s2u(smem);
    const unsigned sbB = sb + 2 * ABYTES;
    const int tid = threadIdx.x;
    const int m0 = blockIdx.y * 128, z = blockIdx.z;
    float* ab = attn + (size_t)z * SEQ * SEQ;
    const size_t bo = (size_t)z * DK * SEQ;
    const size_t co = (size_t)(z >> 4) * SEQ * D_MODEL + (size_t)(z & 15) * DK;

    const int lane = tid & 31, w = tid >> 5;
    const int warp_m = w & 3, warp_n = w >> 2;

    float acc[2][NT][4];
    unsigned accl[2][NT][2];
#pragma unroll
    for (int mt = 0; mt < 2; mt++)
#pragma unroll
        for (int nt = 0; nt < NT; nt++) {
#pragma unroll
            for (int e = 0; e < 4; e++) acc[mt][nt][e] = 0.f;
            accl[mt][nt][0] = 0u; accl[mt][nt][1] = 0u;
        }

    const int arow = tid >> 3, ac4 = tid & 7;
    float2 ms[4];
#pragma unroll
    for (int i = 0; i < 4; i++) ms[i] = MS[(size_t)z * SEQ + m0 + arow + i * 32];

    float4 ra[4];
    auto loadA = [&](int c){
#pragma unroll
        for (int i = 0; i < 4; i++)
            ra[i] = *(const float4*)(ab + (size_t)(m0 + arow + i * 32) * SEQ + c * 32 + ac4 * 4);
    };
    auto storeA = [&](int c, int buf){
        char* bp = smem + buf * ABYTES;
#pragma unroll
        for (int i = 0; i < 4; i++) {
            float4 p;
            p.x = __expf(ra[i].x - ms[i].x) * ms[i].y;
            p.y = __expf(ra[i].y - ms[i].x) * ms[i].y;
            p.z = __expf(ra[i].z - ms[i].x) * ms[i].y;
            p.w = __expf(ra[i].w - ms[i].x) * ms[i].y;
            *(float4*)(ab + (size_t)(m0 + arow + i * 32) * SEQ + c * 32 + ac4 * 4) = p;
            __half2 h0 = __halves2half2(__float2half_rn(p.x), __float2half_rn(p.y));
            __half2 h1 = __halves2half2(__float2half_rn(p.z), __float2half_rn(p.w));
            uint2 uh;
            uh.x = *(unsigned*)&h0; uh.y = *(unsigned*)&h1;
            *(uint2*)(bp + (arow + i * 32) * 80 + ac4 * 8) = uh;
        }
    };
    auto loadB = [&](int c, int buf){
        unsigned sbuf = sbB + buf * BSTG;
        int row = tid >> 2, ch = tid & 3;
        unsigned so = row * 80 + ch * 16;
        cpa(sbuf + so,          Bh + bo + (size_t)row * SEQ + c * 32 + ch * 8);
        cpa(sbuf + BBYTES + so, Bl + bo + (size_t)row * SEQ + c * 32 + ch * 8);
    };

    loadA(0);
    loadB(0, 0);
    asm volatile("cp.async.commit_group;");
    loadB(1, 1);
    asm volatile("cp.async.commit_group;");

    const int nchunk = SEQ / 32;
    for (int c = 0; c < nchunk; c++) {
        storeA(c, c & 1);
        if (c + 1 < nchunk) loadA(c + 1);
        if (c + 1 < nchunk) asm volatile("cp.async.wait_group 1;");
        else                asm volatile("cp.async.wait_group 0;");
        __syncthreads();
        if (c + 2 < nchunk) {
            loadB(c + 2, (c + 2) % 3);
            asm volatile("cp.async.commit_group;");
        }

        unsigned sa  = sb + (c & 1) * ABYTES
                     + (warp_m * 32 + (lane & 15)) * 80 + (lane >> 4) * 16;
        unsigned sbb = sbB + (c % 3) * BSTG
                     + (warp_n * 32 + (lane & 7) + ((lane >> 4) << 3)) * 80
                     + ((lane >> 3) & 1) * 16;
#pragma unroll
        for (int ks = 0; ks < 2; ks++) {
            unsigned ah[2][4];
            ldmx4(ah[0], sa + ks * 32);
            ldmx4(ah[1], sa + 16 * 80 + ks * 32);
#pragma unroll
            for (int p = 0; p < 2; p++) {
                unsigned bh[4], bl[4];
                ldmx4(bh, sbb + p * 16 * 80 + ks * 32);
                ldmx4(bl, sbb + BBYTES + p * 16 * 80 + ks * 32);
#pragma unroll
                for (int mt = 0; mt < 2; mt++)
#pragma unroll
                    for (int t = 0; t < 2; t++) {
                        mma16816(acc[mt][2 * p + t], ah[mt], bh[2 * t], bh[2 * t + 1]);
                        mma16816h(accl[mt][2 * p + t], ah[mt], bl[2 * t], bl[2 * t + 1]);
                    }
            }
        }
    }

    const int g = lane >> 2, q = lane & 3;
#pragma unroll
    for (int mt = 0; mt < 2; mt++) {
        int r0 = m0 + warp_m * 32 + mt * 16 + g;
#pragma unroll
        for (int nt = 0; nt < NT; nt++) {
            float2 l0 = h2f2(accl[mt][nt][0]);
            float2 l1 = h2f2(accl[mt][nt][1]);
            int col = warp_n * 32 + nt * 8 + q * 2;
            size_t o0 = co + (size_t)r0 * D_MODEL + col;
            size_t o1 = co + (size_t)(r0 + 8) * D_MODEL + col;
            split_h(acc[mt][nt][0] + l0.x, acc[mt][nt][1] + l0.y, Chi + o0, nullptr);
            split_h(acc[mt][nt][2] + l1.x, acc[mt][nt][3] + l1.y, Chi + o1, nullptr);
        }
    }
}

// ---------------- fp32 -> fp16 (hi only) ----------------
__global__ void __launch_bounds__(256) conv_h(const float* __restrict__ in,
                                              __half* __restrict__ oh, int n4)
{
    int i = blockIdx.x * 256 + threadIdx.x;
    if (i >= n4) return;
    float4 v = ((const float4*)in)[i];
    ((__half2*)oh)[i * 2]     = __halves2half2(__float2half_rn(v.x), __float2half_rn(v.y));
    ((__half2*)oh)[i * 2 + 1] = __halves2half2(__float2half_rn(v.z), __float2half_rn(v.w));
}

// ---------------- transpose fp32 [R][C] -> fp16 hi/lo [C][R], with scale ----------------
__global__ void transp_split(const float* __restrict__ in, int ild,
                             __half* __restrict__ oh, __half* __restrict__ ol,
                             int old_, float scale)
{
    __shared__ float t[32][33];
    int r0 = blockIdx.y * 32, c0 = blockIdx.x * 32;
    int tx = threadIdx.x, ty = threadIdx.y;
#pragma unroll
    for (int i = 0; i < 32; i += 8) t[ty + i][tx] = in[(size_t)(r0 + ty + i) * ild + c0 + tx] * scale;
    __syncthreads();
#pragma unroll
    for (int i = 0; i < 32; i += 8) {
        float v = t[tx][ty + i];
        __half hh = __float2half_rn(v);
        size_t o = (size_t)(c0 + ty + i) * old_ + r0 + tx;
        oh[o] = hh;
        ol[o] = __float2half_rn(v - __half2float(hh));
    }
}

// ---------------- fused QKV weight transpose ----------------
__global__ void transp_w3(const float* __restrict__ Wq, const float* __restrict__ Wk,
                          const float* __restrict__ Wv,
                          __half* __restrict__ oh, __half* __restrict__ ol)
{
    __shared__ float t[32][33];
    int z = blockIdx.z;
    const float* in = (z == 0) ? Wq : (z == 1) ? Wk : Wv;
    float scale = (z == 0) ? 0.125f : 1.0f;
    size_t ob = (size_t)z * D_MODEL * D_MODEL;
    int r0 = blockIdx.y * 32, c0 = blockIdx.x * 32;
    int tx = threadIdx.x, ty = threadIdx.y;
#pragma unroll
    for (int i = 0; i < 32; i += 8) t[ty + i][tx] = in[(size_t)(r0 + ty + i) * D_MODEL + c0 + tx] * scale;
    __syncthreads();
#pragma unroll
    for (int i = 0; i < 32; i += 8) {
        float v = t[tx][ty + i];
        __half hh = __float2half_rn(v);
        size_t o = ob + (size_t)(c0 + ty + i) * D_MODEL + r0 + tx;
        oh[o] = hh;
        ol[o] = __float2half_rn(v - __half2float(hh));
    }
}

// ---------------- per-head V transpose from split-fp16 QKV ----------------
__global__ void transp_v(const __half* __restrict__ ih, const __half* __restrict__ il,
                         __half* __restrict__ oh, __half* __restrict__ ol)
{
    __shared__ __half th[32][33], tl[32][33];
    int z = blockIdx.z, b = z >> 4, h = z & 15;
    const size_t ib = (size_t)b * SEQ * QKV3 + 2048 + (size_t)h * DK;
    const size_t ob = (size_t)z * DK * SEQ;
    int r0 = blockIdx.y * 32, c0 = blockIdx.x * 32;
    int tx = threadIdx.x, ty = threadIdx.y;
#pragma unroll
    for (int i = 0; i < 32; i += 8) {
        size_t o = ib + (size_t)(r0 + ty + i) * QKV3 + c0 + tx;
        th[ty + i][tx] = ih[o];
        tl[ty + i][tx] = il[o];
    }
    __syncthreads();
#pragma unroll
    for (int i = 0; i < 32; i += 8) {
        size_t o = ob + (size_t)(c0 + ty + i) * SEQ + r0 + tx;
        oh[o] = th[tx][ty + i];
        ol[o] = tl[tx][ty + i];
    }
}

// ---------------- out = LayerNorm(X + Y), optional fp16 hi output ----------------
template<int SPLIT>
__global__ void __launch_bounds__(256) add_ln_kernel(const float* __restrict__ X,
                                                     const float* __restrict__ Y,
                                                     const float* __restrict__ gamma,
                                                     const float* __restrict__ beta,
                                                     float* __restrict__ out,
                                                     __half* __restrict__ oh)
{
    const int row = blockIdx.x;
    const int tid = threadIdx.x;
    const int lane = tid & 31, wid = tid >> 5;
    __shared__ float red[8];

    const float* xr = X + (size_t)row * D_MODEL;
    const float* yr = Y + (size_t)row * D_MODEL;
    float4 xv = *(const float4*)(xr + tid * 4);
    float4 yv = *(const float4*)(yr + tid * 4);
    float v0 = xv.x + yv.x, v1 = xv.y + yv.y, v2 = xv.z + yv.z, v3 = xv.w + yv.w;

    float s = v0 + v1 + v2 + v3;
#pragma unroll
    for (int o = 16; o > 0; o >>= 1) s += __shfl_xor_sync(0xffffffffu, s, o);
    if (lane == 0) red[wid] = s;
    __syncthreads();
    float tot = 0.f;
#pragma unroll
    for (int w = 0; w < 8; w++) tot += red[w];
    float mu = tot * (1.0f / D_MODEL);
    __syncthreads();

    float d0 = v0 - mu, d1 = v1 - mu, d2 = v2 - mu, d3 = v3 - mu;
    float sq = d0 * d0 + d1 * d1 + d2 * d2 + d3 * d3;
#pragma unroll
    for (int o = 16; o > 0; o >>= 1) sq += __shfl_xor_sync(0xffffffffu, sq, o);
    if (lane == 0) red[wid] = sq;
    __syncthreads();
    float vtot = 0.f;
#pragma unroll
    for (int w = 0; w < 8; w++) vtot += red[w];
    float inv = rsqrtf(vtot * (1.0f / D_MODEL) + EPS);

    float4 gv = *(const float4*)(gamma + tid * 4);
    float4 bv = *(const float4*)(beta + tid * 4);
    float o0 = d0 * inv * gv.x + bv.x;
    float o1 = d1 * inv * gv.y + bv.y;
    float o2 = d2 * inv * gv.z + bv.z;
    float o3 = d3 * inv * gv.w + bv.w;
    float4 o4; o4.x = o0; o4.y = o1; o4.z = o2; o4.w = o3;
    *(float4*)(out + (size_t)row * D_MODEL + tid * 4) = o4;
    if (SPLIT) {
        size_t base = (size_t)row * D_MODEL + tid * 4;
        ((__half2*)(oh + base))[0] = __halves2half2(__float2half_rn(o0), __float2half_rn(o1));
        ((__half2*)(oh + base))[1] = __halves2half2(__float2half_rn(o2), __float2half_rn(o3));
    }
}

// ---------------- host ----------------
#define GETP(var, sym) void* var; cudaGetSymbolAddress(&var, sym)
#define HF(p) ((__half*)(p))

extern "C" void kernel_launch(void* const* d_in, const int* in_sizes, int n_in,
                              void* d_out, int out_size)
{
    const float* x   = (const float*)d_in[0];
    const int*   msk = (const int*)  d_in[1];
    const float* Wq  = (const float*)d_in[2];
    const float* bq  = (const float*)d_in[3];
    const float* Wk  = (const float*)d_in[4];
    const float* bk  = (const float*)d_in[5];
    const float* Wv  = (const float*)d_in[6];
    const float* bv  = (const float*)d_in[7];
    const float* Wo  = (const float*)d_in[8];
    const float* bo  = (const float*)d_in[9];
    const float* g1  = (const float*)d_in[10];
    const float* be1 = (const float*)d_in[11];
    const float* W1  = (const float*)d_in[12];
    const float* b1  = (const float*)d_in[13];
    const float* W2  = (const float*)d_in[14];
    const float* b2  = (const float*)d_in[15];
    const float* g2  = (const float*)d_in[16];
    const float* be2 = (const float*)d_in[17];
    float* out = (float*)d_out;

    GETP(pT, g_t);      GETP(pH, g_h);     GETP(pAf, g_attn_f32);
    GETP(pSt, g_stats); GETP(pMS, g_MS);
    GETP(pxh, g_xc_h);
    GETP(pWh, g_Wqkv_h); GETP(pWl, g_Wqkv_l);
    GETP(pWoh, g_Wot_h); GETP(pWol, g_Wot_l);
    GETP(pW1h, g_W1t_h); GETP(pW1l, g_W1t_l);
    GETP(pW2h, g_W2t_h); GETP(pW2l, g_W2t_l);
    GETP(pQKVh, g_qkv_h); GETP(pQKVl, g_qkv_l);
    GETP(pVth, g_Vt_h); GETP(pVtl, g_Vt_l);
    GETP(pCh, g_ctx_h);
    GETP(pHh, g_hc_h);
    GETP(pFh, g_ff_h);

    const size_t OUT_ELEMS  = (size_t)ROWS * D_MODEL;
    const size_t ATTN_ELEMS = (size_t)HZ * SEQ * SEQ;
    float* attn = ((size_t)out_size >= OUT_ELEMS + ATTN_ELEMS) ? out + OUT_ELEMS : (float*)pAf;

    const int SMG  = 3 * (128 * 80 + 2 * 64 * 80);            // 61440
    const int SMCTX = 2 * (128 * 80) + 3 * (2 * 64 * 80);     // 51200
    cudaFuncSetAttribute(gemm_mm<5,0,0,0>, cudaFuncAttributeMaxDynamicSharedMemorySize, SMG);
    cudaFuncSetAttribute(gemm_mm<3,1,1,0>, cudaFuncAttributeMaxDynamicSharedMemorySize, SMG);
    cudaFuncSetAttribute(gemm_mm<0,0,0,0>, cudaFuncAttributeMaxDynamicSharedMemorySize, SMG);
    cudaFuncSetAttribute(gemm_mm<2,0,0,0>, cudaFuncAttributeMaxDynamicSharedMemorySize, SMG);
    cudaFuncSetAttribute(ctx_mm,           cudaFuncAttributeMaxDynamicSharedMemorySize, SMCTX);

    dim3 blk(256);
    dim3 tblk(32, 8);

    // 0: x -> fp16 hi
    conv_h<<<ROWS * D_MODEL / 4 / 256, blk>>>(x, HF(pxh), ROWS * D_MODEL / 4);
    // 1: QKV weights fused transpose (Wq pre-scaled by 0.125)
    transp_w3<<<dim3(32, 32, 3), tblk>>>(Wq, Wk, Wv, HF(pWh), HF(pWl));
    // 2: Wo transpose
    transp_split<<<dim3(32, 32), tblk>>>(Wo, D_MODEL, HF(pWoh), HF(pWol), D_MODEL, 1.0f);
    // 3: fused QKV GEMM
    gemm_mm<5,0,0,0><<<dim3(QKV3 / 64, 32, 1), blk, SMG>>>(
        HF(pxh), D_MODEL, 0, HF(pWh), HF(pWl), D_MODEL, 0,
        nullptr, HF(pQKVh), HF(pQKVl), 0, QKV3, bq, bk, bv, nullptr, nullptr, D_MODEL);
    // 4: scores GEMM + per-tile stats
    gemm_mm<3,1,1,0><<<dim3(32, 16, HZ), blk, SMG>>>(
        HF(pQKVh), QKV3, 0, HF(pQKVh), HF(pQKVl), QKV3, 1024,
        attn, nullptr, nullptr, (long long)SEQ * SEQ, SEQ,
        nullptr, nullptr, nullptr, msk, (float2*)pSt, DK);
    // 5: merge stats
    merge_stats<<<HZ * SEQ / 256, blk>>>((const float2*)pSt, (float2*)pMS);
    // 6: V per-head transpose
    transp_v<<<dim3(2, 64, HZ), tblk>>>(HF(pQKVh), HF(pQKVl), HF(pVth), HF(pVtl));
    // 7: ctx (softmax fused)
    ctx_mm<<<dim3(1, 16, HZ), blk, SMCTX>>>(attn, (const float2*)pMS,
                                            HF(pVth), HF(pVtl), HF(pCh));
    // 8: O-proj, 9: LN1
    gemm_mm<0,0,0,0><<<dim3(16, 32, 1), blk, SMG>>>(
        HF(pCh), D_MODEL, 0, HF(pWoh), HF(pWol), D_MODEL, 0,
        (float*)pT, nullptr, nullptr, 0, D_MODEL, bo, nullptr, nullptr, nullptr, nullptr, D_MODEL);
    add_ln_kernel<1><<<ROWS, blk>>>(x, (const float*)pT, g1, be1, (float*)pH, HF(pHh));
    // 10-11: FFN weights
    transp_split<<<dim3(128, 32), tblk>>>(W1, DFF,     HF(pW1h), HF(pW1l), D_MODEL, 1.0f);
    transp_split<<<dim3(32, 128), tblk>>>(W2, D_MODEL, HF(pW2h), HF(pW2l), DFF, 1.0f);
    // 12: FF1, 13: FF2, 14: LN2
    gemm_mm<2,0,0,0><<<dim3(64, 32, 1), blk, SMG>>>(
        HF(pHh), D_MODEL, 0, HF(pW1h), HF(pW1l), D_MODEL, 0,
        nullptr, HF(pFh), nullptr, 0, DFF, b1, nullptr, nullptr, nullptr, nullptr, D_MODEL);
    gemm_mm<0,0,0,0><<<dim3(16, 32, 1), blk, SMG>>>(
        HF(pFh), DFF, 0, HF(pW2h), HF(pW2l), DFF, 0,
        (float*)pT, nullptr, nullptr, 0, D_MODEL, b2, nullptr, nullptr, nullptr, nullptr, DFF);
    add_ln_kernel<0><<<ROWS, blk>>>((const float*)pH, (const float*)pT, g2, be2, out, nullptr);
}

// round 13
// speedup vs baseline: 1.1504x; 1.1504x over previous
#include <cuda_runtime.h>
#include <cuda_fp16.h>
#include <math.h>

#define D_MODEL 1024
#define NHEAD   16
#define DK      64
#define DFF     4096
#define SEQ     2048
#define BATCH   2
#define ROWS    (BATCH*SEQ)
#define EPS     1e-5f
#define HZ      (BATCH*NHEAD)
#define QKV3    3072

// ---------------- scratch (no allocation allowed) ----------------
__device__ __align__(256) float g_t [(size_t)ROWS*D_MODEL];
__device__ __align__(256) float g_h [(size_t)ROWS*D_MODEL];
__device__ __align__(256) float g_attn_f32[(size_t)HZ*SEQ*SEQ];  // fallback only
__device__ __align__(256) float2 g_stats[(size_t)HZ*32*SEQ];
__device__ __align__(256) float2 g_MS[(size_t)HZ*SEQ];
__device__ __align__(256) __half g_xc_h [(size_t)ROWS*D_MODEL];
__device__ __align__(256) __half g_Wqkv_h[(size_t)QKV3*D_MODEL], g_Wqkv_l[(size_t)QKV3*D_MODEL];
__device__ __align__(256) __half g_Wot_h[(size_t)D_MODEL*D_MODEL], g_Wot_l[(size_t)D_MODEL*D_MODEL];
__device__ __align__(256) __half g_W1t_h[(size_t)D_MODEL*DFF],     g_W1t_l[(size_t)D_MODEL*DFF];
__device__ __align__(256) __half g_W2t_h[(size_t)D_MODEL*DFF],     g_W2t_l[(size_t)D_MODEL*DFF];
__device__ __align__(256) __half g_qkv_h[(size_t)ROWS*QKV3], g_qkv_l[(size_t)ROWS*QKV3];
__device__ __align__(256) __half g_Vt_h [(size_t)HZ*DK*SEQ],  g_Vt_l [(size_t)HZ*DK*SEQ];
__device__ __align__(256) __half g_ctx_h[(size_t)ROWS*D_MODEL];
__device__ __align__(256) __half g_hc_h [(size_t)ROWS*D_MODEL];
__device__ __align__(256) __half g_ff_h [(size_t)ROWS*DFF];

// ---------------- helpers ----------------
__device__ __forceinline__ unsigned s2u(const void* p){
    unsigned a;
    asm("{ .reg .u64 t; cvta.to.shared.u64 t, %1; cvt.u32.u64 %0, t; }" : "=r"(a) : "l"(p));
    return a;
}
__device__ __forceinline__ void cpa(unsigned s, const void* g){
    asm volatile("cp.async.cg.shared.global [%0], [%1], 16;" :: "r"(s), "l"(g));
}
__device__ __forceinline__ void ldmx4(unsigned* r, unsigned addr){
    asm volatile("ldmatrix.sync.aligned.m8n8.x4.shared.b16 {%0,%1,%2,%3}, [%4];"
        : "=r"(r[0]), "=r"(r[1]), "=r"(r[2]), "=r"(r[3]) : "r"(addr));
}
__device__ __forceinline__ void mma16816(float* c, const unsigned* a, unsigned b0, unsigned b1){
    asm volatile("mma.sync.aligned.m16n8k16.row.col.f32.f16.f16.f32 "
        "{%0,%1,%2,%3}, {%4,%5,%6,%7}, {%8,%9}, {%0,%1,%2,%3};"
        : "+f"(c[0]), "+f"(c[1]), "+f"(c[2]), "+f"(c[3])
        : "r"(a[0]), "r"(a[1]), "r"(a[2]), "r"(a[3]), "r"(b0), "r"(b1));
}
__device__ __forceinline__ void split_h(float v0, float v1, __half* hi, __half* lo){
    __half h0 = __float2half_rn(v0), h1 = __float2half_rn(v1);
    *(__half2*)hi = __halves2half2(h0, h1);
    if (lo)
        *(__half2*)lo = __halves2half2(__float2half_rn(v0 - __half2float(h0)),
                                       __float2half_rn(v1 - __half2float(h1)));
}

// ================= 2-term split-fp16 HMMA GEMM =================
// CTA tile 128x64, K-chunk 32, 8 warps, warp tile 32x32, 3-stage cp.async, 1 sync/iter, 3 CTAs/SM.
// EPI: 0 fp32+bias | 2 f16+bias+relu (hi only) | 3 fp32+mask+row-stats | 5 f16split 3-seg bias (QKV)
template<int EPI, int AOFF, int BOFF, int COFF>
__global__ void __launch_bounds__(256, 3) gemm_mm(
    const __half* __restrict__ Ah, int lda, long long sAz,
    const __half* __restrict__ Bh, const __half* __restrict__ Bl, int ldb, long long sBz,
    float* __restrict__ Cf, __half* __restrict__ Chi, __half* __restrict__ Clo,
    long long sCz, int ldc,
    const float* __restrict__ bias, const float* __restrict__ bias2, const float* __restrict__ bias3,
    const int* __restrict__ mask, float2* __restrict__ stats, int K)
{
    constexpr int BN = 64;
    constexpr int NT = 4;
    constexpr int ABYTES = 128 * 80;
    constexpr int BBYTES = BN * 80;
    constexpr int BUFB = ABYTES + 2 * BBYTES;   // 20480
    extern __shared__ __align__(128) char smem[];
    const unsigned sb = s2u(smem);
    const int tid = threadIdx.x;
    const int m0 = blockIdx.y * 128, n0 = blockIdx.x * BN, z = blockIdx.z;

    size_t ao = (AOFF == 1) ? ((size_t)(z >> 4) * SEQ * lda + (size_t)(z & 15) * DK + (size_t)sAz)
                            : (size_t)z * sAz;
    size_t bo = (BOFF == 1) ? ((size_t)(z >> 4) * SEQ * ldb + (size_t)(z & 15) * DK + (size_t)sBz)
                            : (size_t)z * sBz;
    size_t co = (COFF == 1) ? ((size_t)(z >> 4) * SEQ * ldc + (size_t)(z & 15) * DK)
                            : (size_t)z * sCz;

    const int lane = tid & 31, w = tid >> 5;
    const int warp_m = w & 3, warp_n = w >> 2;

    float acc[2][NT][4];
#pragma unroll
    for (int mt = 0; mt < 2; mt++)
#pragma unroll
        for (int nt = 0; nt < NT; nt++)
#pragma unroll
            for (int e = 0; e < 4; e++) acc[mt][nt][e] = 0.f;

    const int nchunk = K >> 5;

    auto load_tile = [&](int c, int buf) {
        unsigned sbuf = sb + buf * BUFB;
        const __half* pah = Ah + ao + (size_t)m0 * lda + c * 32;
#pragma unroll
        for (int i = 0; i < 2; i++) {
            int idx = tid + i * 256;
            int row = idx >> 2, ch = idx & 3;
            cpa(sbuf + row * 80 + ch * 16, pah + (size_t)row * lda + ch * 8);
        }
        const __half* pbh = Bh + bo + (size_t)n0 * ldb + c * 32;
        const __half* pbl = Bl + bo + (size_t)n0 * ldb + c * 32;
        {
            int row = tid >> 2, ch = tid & 3;
            unsigned so = row * 80 + ch * 16;
            cpa(sbuf + ABYTES + so,          pbh + (size_t)row * ldb + ch * 8);
            cpa(sbuf + ABYTES + BBYTES + so, pbl + (size_t)row * ldb + ch * 8);
        }
    };

    auto compute = [&](unsigned sbuf) {
        unsigned sa  = sbuf + (warp_m * 32 + (lane & 15)) * 80 + (lane >> 4) * 16;
        unsigned sbb = sbuf + ABYTES
                     + (warp_n * 32 + (lane & 7) + ((lane >> 4) << 3)) * 80
                     + ((lane >> 3) & 1) * 16;
#pragma unroll
        for (int ks = 0; ks < 2; ks++) {
            unsigned ah[2][4];
            ldmx4(ah[0], sa + ks * 32);
            ldmx4(ah[1], sa + 16 * 80 + ks * 32);
#pragma unroll
            for (int p = 0; p < 2; p++) {
                unsigned bh[4], bl[4];
                ldmx4(bh, sbb + p * 16 * 80 + ks * 32);
                ldmx4(bl, sbb + BBYTES + p * 16 * 80 + ks * 32);
#pragma unroll
                for (int mt = 0; mt < 2; mt++)
#pragma unroll
                    for (int t = 0; t < 2; t++) {
                        float* cc = acc[mt][2 * p + t];
                        mma16816(cc, ah[mt], bh[2 * t], bh[2 * t + 1]);
                        mma16816(cc, ah[mt], bl[2 * t], bl[2 * t + 1]);
                    }
            }
        }
    };

    load_tile(0, 0);
    asm volatile("cp.async.commit_group;");
    if (nchunk > 1) { load_tile(1, 1); asm volatile("cp.async.commit_group;"); }
    for (int c = 0; c < nchunk; c++) {
        if (c + 1 < nchunk) asm volatile("cp.async.wait_group 1;");
        else                asm volatile("cp.async.wait_group 0;");
        __syncthreads();
        if (c + 2 < nchunk) {
            load_tile(c + 2, (c + 2) % 3);
            asm volatile("cp.async.commit_group;");
        }
        compute(sb + (c % 3) * BUFB);
    }

    // -------- epilogue --------
    const int g = lane >> 2, q = lane & 3;
    if (EPI == 3) {
        __syncthreads();
        float* stg = (float*)smem;             // 128 x 64, pitch 68
#pragma unroll
        for (int mt = 0; mt < 2; mt++) {
            int sr = warp_m * 32 + mt * 16 + g;
#pragma unroll
            for (int nt = 0; nt < NT; nt++) {
                int sc = warp_n * 32 + nt * 8 + q * 2;
                stg[sr * 68 + sc]           = acc[mt][nt][0];
                stg[sr * 68 + sc + 1]       = acc[mt][nt][1];
                stg[(sr + 8) * 68 + sc]     = acc[mt][nt][2];
                stg[(sr + 8) * 68 + sc + 1] = acc[mt][nt][3];
            }
        }
        __syncthreads();
        const int* mrow = mask + (size_t)(z >> 4) * SEQ;
#pragma unroll
        for (int i = 0; i < 8; i++) {
            int idx = tid + i * 256, row = idx >> 4, c4 = (idx & 15) * 4;
            float4 v;
            v.x = stg[row * 68 + c4];
            v.y = stg[row * 68 + c4 + 1];
            v.z = stg[row * 68 + c4 + 2];
            v.w = stg[row * 68 + c4 + 3];
            int4 mk = *(const int4*)(mrow + n0 + c4);
            v.x = mk.x ? v.x : -1e9f;
            v.y = mk.y ? v.y : -1e9f;
            v.z = mk.z ? v.z : -1e9f;
            v.w = mk.w ? v.w : -1e9f;
            *(float4*)(Cf + co + (size_t)(m0 + row) * ldc + n0 + c4) = v;
        }
        {
            int row = tid >> 1, half = tid & 1;
            float m = -3.4e38f;
#pragma unroll 8
            for (int c2 = 0; c2 < 32; c2++) {
                float xv = stg[row * 68 + half * 32 + c2];
                if (mrow[n0 + half * 32 + c2] == 0) xv = -1e9f;
                m = fmaxf(m, xv);
            }
            float m2 = fmaxf(m, __shfl_xor_sync(0xffffffffu, m, 1));
            float s = 0.f;
#pragma unroll 8
            for (int c2 = 0; c2 < 32; c2++) {
                float xv = stg[row * 68 + half * 32 + c2];
                if (mrow[n0 + half * 32 + c2] == 0) xv = -1e9f;
                s += __expf(xv - m2);
            }
            s += __shfl_xor_sync(0xffffffffu, s, 1);
            if (half == 0)
                stats[((size_t)z * 32 + blockIdx.x) * SEQ + m0 + row] = make_float2(m2, s);
        }
        return;
    }
#pragma unroll
    for (int mt = 0; mt < 2; mt++) {
        int r0 = m0 + warp_m * 32 + mt * 16 + g;
#pragma unroll
        for (int nt = 0; nt < NT; nt++) {
            int col = n0 + warp_n * 32 + nt * 8 + q * 2;
            float c0 = acc[mt][nt][0], c1 = acc[mt][nt][1];
            float c2 = acc[mt][nt][2], c3 = acc[mt][nt][3];
            if (EPI == 0) {
                float b0v = bias[col], b1v = bias[col + 1];
                float2 v0, v1;
                v0.x = c0 + b0v; v0.y = c1 + b1v;
                v1.x = c2 + b0v; v1.y = c3 + b1v;
                *(float2*)(Cf + co + (size_t)r0 * ldc + col)       = v0;
                *(float2*)(Cf + co + (size_t)(r0 + 8) * ldc + col) = v1;
            } else {
                float b0v, b1v;
                if (EPI == 5) {
                    int seg = col >> 10, cc = col & 1023;
                    const float* bp = (seg == 0) ? bias : ((seg == 1) ? bias2 : bias3);
                    float sc = (seg == 0) ? 0.125f : 1.0f;
                    b0v = bp[cc] * sc; b1v = bp[cc + 1] * sc;
                } else {
                    b0v = bias[col]; b1v = bias[col + 1];
                }
                c0 += b0v; c1 += b1v; c2 += b0v; c3 += b1v;
                if (EPI == 2) {
                    c0 = fmaxf(c0, 0.f); c1 = fmaxf(c1, 0.f);
                    c2 = fmaxf(c2, 0.f); c3 = fmaxf(c3, 0.f);
                }
                size_t o0 = co + (size_t)r0 * ldc + col;
                size_t o1 = co + (size_t)(r0 + 8) * ldc + col;
                split_h(c0, c1, Chi + o0, Clo ? Clo + o0 : nullptr);
                split_h(c2, c3, Chi + o1, Clo ? Clo + o1 : nullptr);
            }
        }
    }
}

// ---------------- merge per-tile stats -> per-row (M, 1/S) ----------------
__global__ void __launch_bounds__(256) merge_stats(const float2* __restrict__ stats,
                                                   float2* __restrict__ MS)
{
    int idx = blockIdx.x * 256 + threadIdx.x;
    int z = idx >> 11, r = idx & 2047;
    const float2* sp = stats + (size_t)z * 32 * SEQ + r;
    float M = -3.4e38f;
#pragma unroll
    for (int jt = 0; jt < 32; jt++) M = fmaxf(M, sp[(size_t)jt * SEQ].x);
    float S = 0.f;
#pragma unroll
    for (int jt = 0; jt < 32; jt++) {
        float2 t = sp[(size_t)jt * SEQ];
        S += t.y * __expf(t.x - M);
    }
    MS[(size_t)z * SEQ + r] = make_float2(M, 1.0f / S);
}

// ================= ctx: M=64 tiles for wave balance; softmax fused; 2-term GEMM =================
// 8 warps: warp_m = w&1 (32 rows), warp_n = w>>1 (16 cols). grid (1, 32, HZ) = 1024 CTAs.
__global__ void __launch_bounds__(256, 3) ctx_mm(
    float* __restrict__ attn, const float2* __restrict__ MS,
    const __half* __restrict__ Bh, const __half* __restrict__ Bl,
    __half* __restrict__ Chi)
{
    constexpr int ABYTES = 64 * 80;            // 64 rows (M=64)
    constexpr int BBYTES = 64 * 80;
    constexpr int BSTG = 2 * BBYTES;
    extern __shared__ __align__(128) char smem[];
    const unsigned sb = s2u(smem);
    const unsigned sbB = sb + 2 * ABYTES;
    const int tid = threadIdx.x;
    const int m0 = blockIdx.y * 64, z = blockIdx.z;
    float* ab = attn + (size_t)z * SEQ * SEQ;
    const size_t bo = (size_t)z * DK * SEQ;
    const size_t co = (size_t)(z >> 4) * SEQ * D_MODEL + (size_t)(z & 15) * DK;

    const int lane = tid & 31, w = tid >> 5;
    const int warp_m = w & 1, warp_n = w >> 1;   // 2 x 4; warp tile 32 x 16

    float acc[2][2][4];
#pragma unroll
    for (int mt = 0; mt < 2; mt++)
#pragma unroll
        for (int nt = 0; nt < 2; nt++)
#pragma unroll
            for (int e = 0; e < 4; e++) acc[mt][nt][e] = 0.f;

    const int arow = tid >> 3, ac4 = tid & 7;    // rows 0..31, +32 for i=1
    float2 ms[2];
#pragma unroll
    for (int i = 0; i < 2; i++) ms[i] = MS[(size_t)z * SEQ + m0 + arow + i * 32];

    float4 ra[2];
    auto loadA = [&](int c){
#pragma unroll
        for (int i = 0; i < 2; i++)
            ra[i] = *(const float4*)(ab + (size_t)(m0 + arow + i * 32) * SEQ + c * 32 + ac4 * 4);
    };
    auto storeA = [&](int c, int buf){
        char* bp = smem + buf * ABYTES;
#pragma unroll
        for (int i = 0; i < 2; i++) {
            float4 p;
            p.x = __expf(ra[i].x - ms[i].x) * ms[i].y;
            p.y = __expf(ra[i].y - ms[i].x) * ms[i].y;
            p.z = __expf(ra[i].z - ms[i].x) * ms[i].y;
            p.w = __expf(ra[i].w - ms[i].x) * ms[i].y;
            *(float4*)(ab + (size_t)(m0 + arow + i * 32) * SEQ + c * 32 + ac4 * 4) = p;
            __half2 h0 = __halves2half2(__float2half_rn(p.x), __float2half_rn(p.y));
            __half2 h1 = __halves2half2(__float2half_rn(p.z), __float2half_rn(p.w));
            uint2 uh;
            uh.x = *(unsigned*)&h0; uh.y = *(unsigned*)&h1;
            *(uint2*)(bp + (arow + i * 32) * 80 + ac4 * 8) = uh;
        }
    };
    auto loadB = [&](int c, int buf){
        unsigned sbuf = sbB + buf * BSTG;
        int row = tid >> 2, ch = tid & 3;
        unsigned so = row * 80 + ch * 16;
        cpa(sbuf + so,          Bh + bo + (size_t)row * SEQ + c * 32 + ch * 8);
        cpa(sbuf + BBYTES + so, Bl + bo + (size_t)row * SEQ + c * 32 + ch * 8);
    };

    loadA(0);
    loadB(0, 0);
    asm volatile("cp.async.commit_group;");
    loadB(1, 1);
    asm volatile("cp.async.commit_group;");

    const int nchunk = SEQ / 32;
    for (int c = 0; c < nchunk; c++) {
        storeA(c, c & 1);
        if (c + 1 < nchunk) loadA(c + 1);
        if (c + 1 < nchunk) asm volatile("cp.async.wait_group 1;");
        else                asm volatile("cp.async.wait_group 0;");
        __syncthreads();
        if (c + 2 < nchunk) {
            loadB(c + 2, (c + 2) % 3);
            asm volatile("cp.async.commit_group;");
        }

        unsigned sa  = sb + (c & 1) * ABYTES
                     + (warp_m * 32 + (lane & 15)) * 80 + (lane >> 4) * 16;
        unsigned sbb = sbB + (c % 3) * BSTG
                     + (warp_n * 16 + (lane & 7) + ((lane >> 4) << 3)) * 80
                     + ((lane >> 3) & 1) * 16;
#pragma unroll
        for (int ks = 0; ks < 2; ks++) {
            unsigned ah[2][4];
            ldmx4(ah[0], sa + ks * 32);
            ldmx4(ah[1], sa + 16 * 80 + ks * 32);
            unsigned bh[4], bl[4];
            ldmx4(bh, sbb + ks * 32);
            ldmx4(bl, sbb + BBYTES + ks * 32);
#pragma unroll
            for (int mt = 0; mt < 2; mt++)
#pragma unroll
                for (int t = 0; t < 2; t++) {
                    float* cc = acc[mt][t];
                    mma16816(cc, ah[mt], bh[2 * t], bh[2 * t + 1]);
                    mma16816(cc, ah[mt], bl[2 * t], bl[2 * t + 1]);
                }
        }
    }

    const int g = lane >> 2, q = lane & 3;
#pragma unroll
    for (int mt = 0; mt < 2; mt++) {
        int r0 = m0 + warp_m * 32 + mt * 16 + g;
#pragma unroll
        for (int nt = 0; nt < 2; nt++) {
            int col = warp_n * 16 + nt * 8 + q * 2;
            size_t o0 = co + (size_t)r0 * D_MODEL + col;
            size_t o1 = co + (size_t)(r0 + 8) * D_MODEL + col;
            split_h(acc[mt][nt][0], acc[mt][nt][1], Chi + o0, nullptr);
            split_h(acc[mt][nt][2], acc[mt][nt][3], Chi + o1, nullptr);
        }
    }
}

// ---------------- fp32 -> fp16 (hi only) ----------------
__global__ void __launch_bounds__(256) conv_h(const float* __restrict__ in,
                                              __half* __restrict__ oh, int n4)
{
    int i = blockIdx.x * 256 + threadIdx.x;
    if (i >= n4) return;
    float4 v = ((const float4*)in)[i];
    ((__half2*)oh)[i * 2]     = __halves2half2(__float2half_rn(v.x), __float2half_rn(v.y));
    ((__half2*)oh)[i * 2 + 1] = __halves2half2(__float2half_rn(v.z), __float2half_rn(v.w));
}

// ---------------- transpose fp32 [R][C] -> fp16 hi/lo [C][R], with scale ----------------
__global__ void transp_split(const float* __restrict__ in, int ild,
                             __half* __restrict__ oh, __half* __restrict__ ol,
                             int old_, float scale)
{
    __shared__ float t[32][33];
    int r0 = blockIdx.y * 32, c0 = blockIdx.x * 32;
    int tx = threadIdx.x, ty = threadIdx.y;
#pragma unroll
    for (int i = 0; i < 32; i += 8) t[ty + i][tx] = in[(size_t)(r0 + ty + i) * ild + c0 + tx] * scale;
    __syncthreads();
#pragma unroll
    for (int i = 0; i < 32; i += 8) {
        float v = t[tx][ty + i];
        __half hh = __float2half_rn(v);
        size_t o = (size_t)(c0 + ty + i) * old_ + r0 + tx;
        oh[o] = hh;
        ol[o] = __float2half_rn(v - __half2float(hh));
    }
}

// ---------------- fused attention weight transpose: Wq(x0.125), Wk, Wv, Wo ----------------
__global__ void transp_w4(const float* __restrict__ Wq, const float* __restrict__ Wk,
                          const float* __restrict__ Wv, const float* __restrict__ Wo,
                          __half* __restrict__ qkv_h, __half* __restrict__ qkv_l,
                          __half* __restrict__ wo_h,  __half* __restrict__ wo_l)
{
    __shared__ float t[32][33];
    int z = blockIdx.z;
    const float* in = (z == 0) ? Wq : (z == 1) ? Wk : (z == 2) ? Wv : Wo;
    float scale = (z == 0) ? 0.125f : 1.0f;
    __half* oh = (z < 3) ? qkv_h + (size_t)z * D_MODEL * D_MODEL : wo_h;
    __half* ol = (z < 3) ? qkv_l + (size_t)z * D_MODEL * D_MODEL : wo_l;
    int r0 = blockIdx.y * 32, c0 = blockIdx.x * 32;
    int tx = threadIdx.x, ty = threadIdx.y;
#pragma unroll
    for (int i = 0; i < 32; i += 8) t[ty + i][tx] = in[(size_t)(r0 + ty + i) * D_MODEL + c0 + tx] * scale;
    __syncthreads();
#pragma unroll
    for (int i = 0; i < 32; i += 8) {
        float v = t[tx][ty + i];
        __half hh = __float2half_rn(v);
        size_t o = (size_t)(c0 + ty + i) * D_MODEL + r0 + tx;
        oh[o] = hh;
        ol[o] = __float2half_rn(v - __half2float(hh));
    }
}

// ---------------- per-head V transpose from split-fp16 QKV ----------------
__global__ void transp_v(const __half* __restrict__ ih, const __half* __restrict__ il,
                         __half* __restrict__ oh, __half* __restrict__ ol)
{
    __shared__ __half th[32][33], tl[32][33];
    int z = blockIdx.z, b = z >> 4, h = z & 15;
    const size_t ib = (size_t)b * SEQ * QKV3 + 2048 + (size_t)h * DK;
    const size_t ob = (size_t)z * DK * SEQ;
    int r0 = blockIdx.y * 32, c0 = blockIdx.x * 32;
    int tx = threadIdx.x, ty = threadIdx.y;
#pragma unroll
    for (int i = 0; i < 32; i += 8) {
        size_t o = ib + (size_t)(r0 + ty + i) * QKV3 + c0 + tx;
        th[ty + i][tx] = ih[o];
        tl[ty + i][tx] = il[o];
    }
    __syncthreads();
#pragma unroll
    for (int i = 0; i < 32; i += 8) {
        size_t o = ob + (size_t)(c0 + ty + i) * SEQ + r0 + tx;
        oh[o] = th[tx][ty + i];
        ol[o] = tl[tx][ty + i];
    }
}

// ---------------- out = LayerNorm(X + Y), optional fp16 hi output ----------------
template<int SPLIT>
__global__ void __launch_bounds__(256) add_ln_kernel(const float* __restrict__ X,
                                                     const float* __restrict__ Y,
                                                     const float* __restrict__ gamma,
                                                     const float* __restrict__ beta,
                                                     float* __restrict__ out,
                                                     __half* __restrict__ oh)
{
    const int row = blockIdx.x;
    const int tid = threadIdx.x;
    const int lane = tid & 31, wid = tid >> 5;
    __shared__ float red[8];

    const float* xr = X + (size_t)row * D_MODEL;
    const float* yr = Y + (size_t)row * D_MODEL;
    float4 xv = *(const float4*)(xr + tid * 4);
    float4 yv = *(const float4*)(yr + tid * 4);
    float v0 = xv.x + yv.x, v1 = xv.y + yv.y, v2 = xv.z + yv.z, v3 = xv.w + yv.w;

    float s = v0 + v1 + v2 + v3;
#pragma unroll
    for (int o = 16; o > 0; o >>= 1) s += __shfl_xor_sync(0xffffffffu, s, o);
    if (lane == 0) red[wid] = s;
    __syncthreads();
    float tot = 0.f;
#pragma unroll
    for (int w = 0; w < 8; w++) tot += red[w];
    float mu = tot * (1.0f / D_MODEL);
    __syncthreads();

    float d0 = v0 - mu, d1 = v1 - mu, d2 = v2 - mu, d3 = v3 - mu;
    float sq = d0 * d0 + d1 * d1 + d2 * d2 + d3 * d3;
#pragma unroll
    for (int o = 16; o > 0; o >>= 1) sq += __shfl_xor_sync(0xffffffffu, sq, o);
    if (lane == 0) red[wid] = sq;
    __syncthreads();
    float vtot = 0.f;
#pragma unroll
    for (int w = 0; w < 8; w++) vtot += red[w];
    float inv = rsqrtf(vtot * (1.0f / D_MODEL) + EPS);

    float4 gv = *(const float4*)(gamma + tid * 4);
    float4 bv = *(const float4*)(beta + tid * 4);
    float o0 = d0 * inv * gv.x + bv.x;
    float o1 = d1 * inv * gv.y + bv.y;
    float o2 = d2 * inv * gv.z + bv.z;
    float o3 = d3 * inv * gv.w + bv.w;
    float4 o4; o4.x = o0; o4.y = o1; o4.z = o2; o4.w = o3;
    *(float4*)(out + (size_t)row * D_MODEL + tid * 4) = o4;
    if (SPLIT) {
        size_t base = (size_t)row * D_MODEL + tid * 4;
        ((__half2*)(oh + base))[0] = __halves2half2(__float2half_rn(o0), __float2half_rn(o1));
        ((__half2*)(oh + base))[1] = __halves2half2(__float2half_rn(o2), __float2half_rn(o3));
    }
}

// ---------------- host ----------------
#define GETP(var, sym) void* var; cudaGetSymbolAddress(&var, sym)
#define HF(p) ((__half*)(p))

extern "C" void kernel_launch(void* const* d_in, const int* in_sizes, int n_in,
                              void* d_out, int out_size)
{
    const float* x   = (const float*)d_in[0];
    const int*   msk = (const int*)  d_in[1];
    const float* Wq  = (const float*)d_in[2];
    const float* bq  = (const float*)d_in[3];
    const float* Wk  = (const float*)d_in[4];
    const float* bk  = (const float*)d_in[5];
    const float* Wv  = (const float*)d_in[6];
    const float* bv  = (const float*)d_in[7];
    const float* Wo  = (const float*)d_in[8];
    const float* bo  = (const float*)d_in[9];
    const float* g1  = (const float*)d_in[10];
    const float* be1 = (const float*)d_in[11];
    const float* W1  = (const float*)d_in[12];
    const float* b1  = (const float*)d_in[13];
    const float* W2  = (const float*)d_in[14];
    const float* b2  = (const float*)d_in[15];
    const float* g2  = (const float*)d_in[16];
    const float* be2 = (const float*)d_in[17];
    float* out = (float*)d_out;

    GETP(pT, g_t);      GETP(pH, g_h);     GETP(pAf, g_attn_f32);
    GETP(pSt, g_stats); GETP(pMS, g_MS);
    GETP(pxh, g_xc_h);
    GETP(pWh, g_Wqkv_h); GETP(pWl, g_Wqkv_l);
    GETP(pWoh, g_Wot_h); GETP(pWol, g_Wot_l);
    GETP(pW1h, g_W1t_h); GETP(pW1l, g_W1t_l);
    GETP(pW2h, g_W2t_h); GETP(pW2l, g_W2t_l);
    GETP(pQKVh, g_qkv_h); GETP(pQKVl, g_qkv_l);
    GETP(pVth, g_Vt_h); GETP(pVtl, g_Vt_l);
    GETP(pCh, g_ctx_h);
    GETP(pHh, g_hc_h);
    GETP(pFh, g_ff_h);

    const size_t OUT_ELEMS  = (size_t)ROWS * D_MODEL;
    const size_t ATTN_ELEMS = (size_t)HZ * SEQ * SEQ;
    float* attn = ((size_t)out_size >= OUT_ELEMS + ATTN_ELEMS) ? out + OUT_ELEMS : (float*)pAf;

    const int SMG  = 3 * (128 * 80 + 2 * 64 * 80);            // 61440
    const int SMCTX = 2 * (64 * 80) + 3 * (2 * 64 * 80);      // 40960
    cudaFuncSetAttribute(gemm_mm<5,0,0,0>, cudaFuncAttributeMaxDynamicSharedMemorySize, SMG);
    cudaFuncSetAttribute(gemm_mm<3,1,1,0>, cudaFuncAttributeMaxDynamicSharedMemorySize, SMG);
    cudaFuncSetAttribute(gemm_mm<0,0,0,0>, cudaFuncAttributeMaxDynamicSharedMemorySize, SMG);
    cudaFuncSetAttribute(gemm_mm<2,0,0,0>, cudaFuncAttributeMaxDynamicSharedMemorySize, SMG);
    cudaFuncSetAttribute(ctx_mm,           cudaFuncAttributeMaxDynamicSharedMemorySize, SMCTX);

    dim3 blk(256);
    dim3 tblk(32, 8);

    // 0: x -> fp16 hi
    conv_h<<<ROWS * D_MODEL / 4 / 256, blk>>>(x, HF(pxh), ROWS * D_MODEL / 4);
    // 1: attention weights fused transpose (Wq x0.125, Wk, Wv, Wo)
    transp_w4<<<dim3(32, 32, 4), tblk>>>(Wq, Wk, Wv, Wo, HF(pWh), HF(pWl), HF(pWoh), HF(pWol));
    // 2: fused QKV GEMM
    gemm_mm<5,0,0,0><<<dim3(QKV3 / 64, 32, 1), blk, SMG>>>(
        HF(pxh), D_MODEL, 0, HF(pWh), HF(pWl), D_MODEL, 0,
        nullptr, HF(pQKVh), HF(pQKVl), 0, QKV3, bq, bk, bv, nullptr, nullptr, D_MODEL);
    // 3: scores GEMM + per-tile stats
    gemm_mm<3,1,1,0><<<dim3(32, 16, HZ), blk, SMG>>>(
        HF(pQKVh), QKV3, 0, HF(pQKVh), HF(pQKVl), QKV3, 1024,
        attn, nullptr, nullptr, (long long)SEQ * SEQ, SEQ,
        nullptr, nullptr, nullptr, msk, (float2*)pSt, DK);
    // 4: merge stats
    merge_stats<<<HZ * SEQ / 256, blk>>>((const float2*)pSt, (float2*)pMS);
    // 5: V per-head transpose
    transp_v<<<dim3(2, 64, HZ), tblk>>>(HF(pQKVh), HF(pQKVl), HF(pVth), HF(pVtl));
    // 6: ctx (softmax fused, M=64 tiles)
    ctx_mm<<<dim3(1, 32, HZ), blk, SMCTX>>>(attn, (const float2*)pMS,
                                            HF(pVth), HF(pVtl), HF(pCh));
    // 7: O-proj, 8: LN1
    gemm_mm<0,0,0,0><<<dim3(16, 32, 1), blk, SMG>>>(
        HF(pCh), D_MODEL, 0, HF(pWoh), HF(pWol), D_MODEL, 0,
        (float*)pT, nullptr, nullptr, 0, D_MODEL, bo, nullptr, nullptr, nullptr, nullptr, D_MODEL);
    add_ln_kernel<1><<<ROWS, blk>>>(x, (const float*)pT, g1, be1, (float*)pH, HF(pHh));
    // 9-10: FFN weights
    transp_split<<<dim3(128, 32), tblk>>>(W1, DFF,     HF(pW1h), HF(pW1l), D_MODEL, 1.0f);
    transp_split<<<dim3(32, 128), tblk>>>(W2, D_MODEL, HF(pW2h), HF(pW2l), DFF, 1.0f);
    // 11: FF1, 12: FF2, 13: LN2
    gemm_mm<2,0,0,0><<<dim3(64, 32, 1), blk, SMG>>>(
        HF(pHh), D_MODEL, 0, HF(pW1h), HF(pW1l), D_MODEL, 0,
        nullptr, HF(pFh), nullptr, 0, DFF, b1, nullptr, nullptr, nullptr, nullptr, D_MODEL);
    gemm_mm<0,0,0,0><<<dim3(16, 32, 1), blk, SMG>>>(
        HF(pFh), DFF, 0, HF(pW2h), HF(pW2l), DFF, 0,
        (float*)pT, nullptr, nullptr, 0, D_MODEL, b2, nullptr, nullptr, nullptr, nullptr, DFF);
    add_ln_kernel<0><<<ROWS, blk>>>((const float*)pH, (const float*)pT, g2, be2, out, nullptr);
}

// round 17
// speedup vs baseline: 1.2025x; 1.0453x over previous
#include <cuda_runtime.h>
#include <cuda_fp16.h>
#include <math.h>

#define D_MODEL 1024
#define NHEAD   16
#define DK      64
#define DFF     4096
#define SEQ     2048
#define BATCH   2
#define ROWS    (BATCH*SEQ)
#define EPS     1e-5f
#define HZ      (BATCH*NHEAD)
#define QKV3    3072

// ---------------- scratch (no allocation allowed) ----------------
__device__ __align__(256) float g_t [(size_t)ROWS*D_MODEL];
__device__ __align__(256) float g_h [(size_t)ROWS*D_MODEL];
__device__ __align__(256) float g_attn_f32[(size_t)HZ*SEQ*SEQ];  // fallback only
__device__ __align__(256) float2 g_stats[(size_t)HZ*32*SEQ];
__device__ __align__(256) float2 g_MS[(size_t)HZ*SEQ];
__device__ __align__(256) __half g_xc_h [(size_t)ROWS*D_MODEL];
__device__ __align__(256) __half g_Wqkv_h[(size_t)QKV3*D_MODEL], g_Wqkv_l[(size_t)QKV3*D_MODEL];
__device__ __align__(256) __half g_Wot_h[(size_t)D_MODEL*D_MODEL], g_Wot_l[(size_t)D_MODEL*D_MODEL];
__device__ __align__(256) __half g_W1t_h[(size_t)D_MODEL*DFF],     g_W1t_l[(size_t)D_MODEL*DFF];
__device__ __align__(256) __half g_W2t_h[(size_t)D_MODEL*DFF],     g_W2t_l[(size_t)D_MODEL*DFF];
__device__ __align__(256) __half g_qkv_h[(size_t)ROWS*QKV3], g_qkv_l[(size_t)ROWS*QKV3];
__device__ __align__(256) __half g_Vt_h [(size_t)HZ*DK*SEQ],  g_Vt_l [(size_t)HZ*DK*SEQ];
__device__ __align__(256) __half g_ctx_h[(size_t)ROWS*D_MODEL];
__device__ __align__(256) __half g_hc_h [(size_t)ROWS*D_MODEL];
__device__ __align__(256) __half g_ff_h [(size_t)ROWS*DFF];

// ---------------- helpers ----------------
__device__ __forceinline__ unsigned s2u(const void* p){
    unsigned a;
    asm("{ .reg .u64 t; cvta.to.shared.u64 t, %1; cvt.u32.u64 %0, t; }" : "=r"(a) : "l"(p));
    return a;
}
__device__ __forceinline__ void cpa(unsigned s, const void* g){
    asm volatile("cp.async.cg.shared.global [%0], [%1], 16;" :: "r"(s), "l"(g));
}
__device__ __forceinline__ void ldmx4(unsigned* r, unsigned addr){
    asm volatile("ldmatrix.sync.aligned.m8n8.x4.shared.b16 {%0,%1,%2,%3}, [%4];"
        : "=r"(r[0]), "=r"(r[1]), "=r"(r[2]), "=r"(r[3]) : "r"(addr));
}
__device__ __forceinline__ void mma16816(float* c, const unsigned* a, unsigned b0, unsigned b1){
    asm volatile("mma.sync.aligned.m16n8k16.row.col.f32.f16.f16.f32 "
        "{%0,%1,%2,%3}, {%4,%5,%6,%7}, {%8,%9}, {%0,%1,%2,%3};"
        : "+f"(c[0]), "+f"(c[1]), "+f"(c[2]), "+f"(c[3])
        : "r"(a[0]), "r"(a[1]), "r"(a[2]), "r"(a[3]), "r"(b0), "r"(b1));
}
__device__ __forceinline__ void split_h(float v0, float v1, __half* hi, __half* lo){
    __half h0 = __float2half_rn(v0), h1 = __float2half_rn(v1);
    *(__half2*)hi = __halves2half2(h0, h1);
    if (lo)
        *(__half2*)lo = __halves2half2(__float2half_rn(v0 - __half2float(h0)),
                                       __float2half_rn(v1 - __half2float(h1)));
}

// ================= 2-term split-fp16 HMMA GEMM =================
// CTA tile 128x64, K-chunk 32, 8 warps, warp tile 32x32, 3-stage cp.async, 1 sync/iter, 3 CTAs/SM.
// EPI: 0 fp32+bias | 2 f16+bias+relu (hi only) | 3 fp32+mask+row-stats | 5 f16split 3-seg bias (QKV)
template<int EPI, int AOFF, int BOFF, int COFF>
__global__ void __launch_bounds__(256, 3) gemm_mm(
    const __half* __restrict__ Ah, int lda, long long sAz,
    const __half* __restrict__ Bh, const __half* __restrict__ Bl, int ldb, long long sBz,
    float* __restrict__ Cf, __half* __restrict__ Chi, __half* __restrict__ Clo,
    long long sCz, int ldc,
    const float* __restrict__ bias, const float* __restrict__ bias2, const float* __restrict__ bias3,
    const int* __restrict__ mask, float2* __restrict__ stats, int K)
{
    constexpr int BN = 64;
    constexpr int NT = 4;
    constexpr int ABYTES = 128 * 80;
    constexpr int BBYTES = BN * 80;
    constexpr int BUFB = ABYTES + 2 * BBYTES;   // 20480
    extern __shared__ __align__(128) char smem[];
    const unsigned sb = s2u(smem);
    const int tid = threadIdx.x;
    const int m0 = blockIdx.y * 128, n0 = blockIdx.x * BN, z = blockIdx.z;

    size_t ao = (AOFF == 1) ? ((size_t)(z >> 4) * SEQ * lda + (size_t)(z & 15) * DK + (size_t)sAz)
                            : (size_t)z * sAz;
    size_t bo = (BOFF == 1) ? ((size_t)(z >> 4) * SEQ * ldb + (size_t)(z & 15) * DK + (size_t)sBz)
                            : (size_t)z * sBz;
    size_t co = (COFF == 1) ? ((size_t)(z >> 4) * SEQ * ldc + (size_t)(z & 15) * DK)
                            : (size_t)z * sCz;

    const int lane = tid & 31, w = tid >> 5;
    const int warp_m = w & 3, warp_n = w >> 2;

    float acc[2][NT][4];
#pragma unroll
    for (int mt = 0; mt < 2; mt++)
#pragma unroll
        for (int nt = 0; nt < NT; nt++)
#pragma unroll
            for (int e = 0; e < 4; e++) acc[mt][nt][e] = 0.f;

    const int nchunk = K >> 5;

    auto load_tile = [&](int c, int buf) {
        unsigned sbuf = sb + buf * BUFB;
        const __half* pah = Ah + ao + (size_t)m0 * lda + c * 32;
#pragma unroll
        for (int i = 0; i < 2; i++) {
            int idx = tid + i * 256;
            int row = idx >> 2, ch = idx & 3;
            cpa(sbuf + row * 80 + ch * 16, pah + (size_t)row * lda + ch * 8);
        }
        const __half* pbh = Bh + bo + (size_t)n0 * ldb + c * 32;
        const __half* pbl = Bl + bo + (size_t)n0 * ldb + c * 32;
        {
            int row = tid >> 2, ch = tid & 3;
            unsigned so = row * 80 + ch * 16;
            cpa(sbuf + ABYTES + so,          pbh + (size_t)row * ldb + ch * 8);
            cpa(sbuf + ABYTES + BBYTES + so, pbl + (size_t)row * ldb + ch * 8);
        }
    };

    auto compute = [&](unsigned sbuf) {
        unsigned sa  = sbuf + (warp_m * 32 + (lane & 15)) * 80 + (lane >> 4) * 16;
        unsigned sbb = sbuf + ABYTES
                     + (warp_n * 32 + (lane & 7) + ((lane >> 4) << 3)) * 80
                     + ((lane >> 3) & 1) * 16;
#pragma unroll
        for (int ks = 0; ks < 2; ks++) {
            unsigned ah[2][4];
            ldmx4(ah[0], sa + ks * 32);
            ldmx4(ah[1], sa + 16 * 80 + ks * 32);
#pragma unroll
            for (int p = 0; p < 2; p++) {
                unsigned bh[4], bl[4];
                ldmx4(bh, sbb + p * 16 * 80 + ks * 32);
                ldmx4(bl, sbb + BBYTES + p * 16 * 80 + ks * 32);
#pragma unroll
                for (int mt = 0; mt < 2; mt++)
#pragma unroll
                    for (int t = 0; t < 2; t++) {
                        float* cc = acc[mt][2 * p + t];
                        mma16816(cc, ah[mt], bh[2 * t], bh[2 * t + 1]);
                        mma16816(cc, ah[mt], bl[2 * t], bl[2 * t + 1]);
                    }
            }
        }
    };

    load_tile(0, 0);
    asm volatile("cp.async.commit_group;");
    if (nchunk > 1) { load_tile(1, 1); asm volatile("cp.async.commit_group;"); }
    for (int c = 0; c < nchunk; c++) {
        if (c + 1 < nchunk) asm volatile("cp.async.wait_group 1;");
        else                asm volatile("cp.async.wait_group 0;");
        __syncthreads();
        if (c + 2 < nchunk) {
            load_tile(c + 2, (c + 2) % 3);
            asm volatile("cp.async.commit_group;");
        }
        compute(sb + (c % 3) * BUFB);
    }

    // -------- epilogue --------
    const int g = lane >> 2, q = lane & 3;
    if (EPI == 3) {
        // mask values for this thread's own columns (8 ints, L1-cached)
        const int* mrow = mask + (size_t)(z >> 4) * SEQ;
        int mkv[NT][2];
#pragma unroll
        for (int nt = 0; nt < NT; nt++) {
            int col = n0 + warp_n * 32 + nt * 8 + q * 2;
            mkv[nt][0] = mrow[col];
            mkv[nt][1] = mrow[col + 1];
        }
        __syncthreads();
        float* stg = (float*)smem;             // 128 x 64, pitch 68 words (272 B, 16B-aligned)
#pragma unroll
        for (int mt = 0; mt < 2; mt++) {
            int sr = warp_m * 32 + mt * 16 + g;
#pragma unroll
            for (int nt = 0; nt < NT; nt++) {
                int sc = warp_n * 32 + nt * 8 + q * 2;
                stg[sr * 68 + sc]           = mkv[nt][0] ? acc[mt][nt][0] : -1e9f;
                stg[sr * 68 + sc + 1]       = mkv[nt][1] ? acc[mt][nt][1] : -1e9f;
                stg[(sr + 8) * 68 + sc]     = mkv[nt][0] ? acc[mt][nt][2] : -1e9f;
                stg[(sr + 8) * 68 + sc + 1] = mkv[nt][1] ? acc[mt][nt][3] : -1e9f;
            }
        }
        __syncthreads();
        // coalesced write (values already masked)
#pragma unroll
        for (int i = 0; i < 8; i++) {
            int idx = tid + i * 256, row = idx >> 4, c4 = (idx & 15) * 4;
            float4 v = *(float4*)(stg + row * 68 + c4);
            *(float4*)(Cf + co + (size_t)(m0 + row) * ldc + n0 + c4) = v;
        }
        // per-tile row stats: 2 threads per row, float4 smem reads
        {
            int row = tid >> 1, half = tid & 1;
            const float* rp = stg + row * 68 + half * 32;
            float m = -3.4e38f;
#pragma unroll
            for (int c4 = 0; c4 < 32; c4 += 4) {
                float4 v = *(const float4*)(rp + c4);
                m = fmaxf(m, fmaxf(fmaxf(v.x, v.y), fmaxf(v.z, v.w)));
            }
            float m2 = fmaxf(m, __shfl_xor_sync(0xffffffffu, m, 1));
            float s = 0.f;
#pragma unroll
            for (int c4 = 0; c4 < 32; c4 += 4) {
                float4 v = *(const float4*)(rp + c4);
                s += __expf(v.x - m2) + __expf(v.y - m2) + __expf(v.z - m2) + __expf(v.w - m2);
            }
            s += __shfl_xor_sync(0xffffffffu, s, 1);
            if (half == 0)
                stats[((size_t)z * 32 + blockIdx.x) * SEQ + m0 + row] = make_float2(m2, s);
        }
        return;
    }
#pragma unroll
    for (int mt = 0; mt < 2; mt++) {
        int r0 = m0 + warp_m * 32 + mt * 16 + g;
#pragma unroll
        for (int nt = 0; nt < NT; nt++) {
            int col = n0 + warp_n * 32 + nt * 8 + q * 2;
            float c0 = acc[mt][nt][0], c1 = acc[mt][nt][1];
            float c2 = acc[mt][nt][2], c3 = acc[mt][nt][3];
            if (EPI == 0) {
                float b0v = bias[col], b1v = bias[col + 1];
                float2 v0, v1;
                v0.x = c0 + b0v; v0.y = c1 + b1v;
                v1.x = c2 + b0v; v1.y = c3 + b1v;
                *(float2*)(Cf + co + (size_t)r0 * ldc + col)       = v0;
                *(float2*)(Cf + co + (size_t)(r0 + 8) * ldc + col) = v1;
            } else {
                float b0v, b1v;
                if (EPI == 5) {
                    int seg = col >> 10, cc = col & 1023;
                    const float* bp = (seg == 0) ? bias : ((seg == 1) ? bias2 : bias3);
                    float sc = (seg == 0) ? 0.125f : 1.0f;
                    b0v = bp[cc] * sc; b1v = bp[cc + 1] * sc;
                } else {
                    b0v = bias[col]; b1v = bias[col + 1];
                }
                c0 += b0v; c1 += b1v; c2 += b0v; c3 += b1v;
                if (EPI == 2) {
                    c0 = fmaxf(c0, 0.f); c1 = fmaxf(c1, 0.f);
                    c2 = fmaxf(c2, 0.f); c3 = fmaxf(c3, 0.f);
                }
                size_t o0 = co + (size_t)r0 * ldc + col;
                size_t o1 = co + (size_t)(r0 + 8) * ldc + col;
                split_h(c0, c1, Chi + o0, Clo ? Clo + o0 : nullptr);
                split_h(c2, c3, Chi + o1, Clo ? Clo + o1 : nullptr);
            }
        }
    }
}

// ---------------- merge per-tile stats -> per-row (M, 1/S) ----------------
__global__ void __launch_bounds__(256) merge_stats(const float2* __restrict__ stats,
                                                   float2* __restrict__ MS)
{
    int idx = blockIdx.x * 256 + threadIdx.x;
    int z = idx >> 11, r = idx & 2047;
    const float2* sp = stats + (size_t)z * 32 * SEQ + r;
    float M = -3.4e38f;
#pragma unroll
    for (int jt = 0; jt < 32; jt++) M = fmaxf(M, sp[(size_t)jt * SEQ].x);
    float S = 0.f;
#pragma unroll
    for (int jt = 0; jt < 32; jt++) {
        float2 t = sp[(size_t)jt * SEQ];
        S += t.y * __expf(t.x - M);
    }
    MS[(size_t)z * SEQ + r] = make_float2(M, 1.0f / S);
}

// ================= ctx: normalize raw scores in place + 2-term GEMM with Vt (M=128) =================
__global__ void __launch_bounds__(256, 3) ctx_mm(
    float* __restrict__ attn, const float2* __restrict__ MS,
    const __half* __restrict__ Bh, const __half* __restrict__ Bl,
    __half* __restrict__ Chi)
{
    constexpr int NT = 4;
    constexpr int ABYTES = 128 * 80;
    constexpr int BBYTES = 64 * 80;
    constexpr int BSTG = 2 * BBYTES;
    extern __shared__ __align__(128) char smem[];
    const unsigned sb = s2u(smem);
    const unsigned sbB = sb + 2 * ABYTES;
    const int tid = threadIdx.x;
    const int m0 = blockIdx.y * 128, z = blockIdx.z;
    float* ab = attn + (size_t)z * SEQ * SEQ;
    const size_t bo = (size_t)z * DK * SEQ;
    const size_t co = (size_t)(z >> 4) * SEQ * D_MODEL + (size_t)(z & 15) * DK;

    const int lane = tid & 31, w = tid >> 5;
    const int warp_m = w & 3, warp_n = w >> 2;

    float acc[2][NT][4];
#pragma unroll
    for (int mt = 0; mt < 2; mt++)
#pragma unroll
        for (int nt = 0; nt < NT; nt++)
#pragma unroll
            for (int e = 0; e < 4; e++) acc[mt][nt][e] = 0.f;

    const int arow = tid >> 3, ac4 = tid & 7;
    float2 ms[4];
#pragma unroll
    for (int i = 0; i < 4; i++) ms[i] = MS[(size_t)z * SEQ + m0 + arow + i * 32];

    float4 ra[4];
    auto loadA = [&](int c){
#pragma unroll
        for (int i = 0; i < 4; i++)
            ra[i] = *(const float4*)(ab + (size_t)(m0 + arow + i * 32) * SEQ + c * 32 + ac4 * 4);
    };
    auto storeA = [&](int c, int buf){
        char* bp = smem + buf * ABYTES;
#pragma unroll
        for (int i = 0; i < 4; i++) {
            float4 p;
            p.x = __expf(ra[i].x - ms[i].x) * ms[i].y;
            p.y = __expf(ra[i].y - ms[i].x) * ms[i].y;
            p.z = __expf(ra[i].z - ms[i].x) * ms[i].y;
            p.w = __expf(ra[i].w - ms[i].x) * ms[i].y;
            *(float4*)(ab + (size_t)(m0 + arow + i * 32) * SEQ + c * 32 + ac4 * 4) = p;
            __half2 h0 = __halves2half2(__float2half_rn(p.x), __float2half_rn(p.y));
            __half2 h1 = __halves2half2(__float2half_rn(p.z), __float2half_rn(p.w));
            uint2 uh;
            uh.x = *(unsigned*)&h0; uh.y = *(unsigned*)&h1;
            *(uint2*)(bp + (arow + i * 32) * 80 + ac4 * 8) = uh;
        }
    };
    auto loadB = [&](int c, int buf){
        unsigned sbuf = sbB + buf * BSTG;
        int row = tid >> 2, ch = tid & 3;
        unsigned so = row * 80 + ch * 16;
        cpa(sbuf + so,          Bh + bo + (size_t)row * SEQ + c * 32 + ch * 8);
        cpa(sbuf + BBYTES + so, Bl + bo + (size_t)row * SEQ + c * 32 + ch * 8);
    };

    loadA(0);
    loadB(0, 0);
    asm volatile("cp.async.commit_group;");
    loadB(1, 1);
    asm volatile("cp.async.commit_group;");

    const int nchunk = SEQ / 32;
    for (int c = 0; c < nchunk; c++) {
        storeA(c, c & 1);
        if (c + 1 < nchunk) loadA(c + 1);
        if (c + 1 < nchunk) asm volatile("cp.async.wait_group 1;");
        else                asm volatile("cp.async.wait_group 0;");
        __syncthreads();
        if (c + 2 < nchunk) {
            loadB(c + 2, (c + 2) % 3);
            asm volatile("cp.async.commit_group;");
        }

        unsigned sa  = sb + (c & 1) * ABYTES
                     + (warp_m * 32 + (lane & 15)) * 80 + (lane >> 4) * 16;
        unsigned sbb = sbB + (c % 3) * BSTG
                     + (warp_n * 32 + (lane & 7) + ((lane >> 4) << 3)) * 80
                     + ((lane >> 3) & 1) * 16;
#pragma unroll
        for (int ks = 0; ks < 2; ks++) {
            unsigned ah[2][4];
            ldmx4(ah[0], sa + ks * 32);
            ldmx4(ah[1], sa + 16 * 80 + ks * 32);
#pragma unroll
            for (int p = 0; p < 2; p++) {
                unsigned bh[4], bl[4];
                ldmx4(bh, sbb + p * 16 * 80 + ks * 32);
                ldmx4(bl, sbb + BBYTES + p * 16 * 80 + ks * 32);
#pragma unroll
                for (int mt = 0; mt < 2; mt++)
#pragma unroll
                    for (int t = 0; t < 2; t++) {
                        float* cc = acc[mt][2 * p + t];
                        mma16816(cc, ah[mt], bh[2 * t], bh[2 * t + 1]);
                        mma16816(cc, ah[mt], bl[2 * t], bl[2 * t + 1]);
                    }
            }
        }
    }

    const int g = lane >> 2, q = lane & 3;
#pragma unroll
    for (int mt = 0; mt < 2; mt++) {
        int r0 = m0 + warp_m * 32 + mt * 16 + g;
#pragma unroll
        for (int nt = 0; nt < NT; nt++) {
            int col = warp_n * 32 + nt * 8 + q * 2;
            size_t o0 = co + (size_t)r0 * D_MODEL + col;
            size_t o1 = co + (size_t)(r0 + 8) * D_MODEL + col;
            split_h(acc[mt][nt][0], acc[mt][nt][1], Chi + o0, nullptr);
            split_h(acc[mt][nt][2], acc[mt][nt][3], Chi + o1, nullptr);
        }
    }
}

// ---------------- fp32 -> fp16 (hi only) ----------------
__global__ void __launch_bounds__(256) conv_h(const float* __restrict__ in,
                                              __half* __restrict__ oh, int n4)
{
    int i = blockIdx.x * 256 + threadIdx.x;
    if (i >= n4) return;
    float4 v = ((const float4*)in)[i];
    ((__half2*)oh)[i * 2]     = __halves2half2(__float2half_rn(v.x), __float2half_rn(v.y));
    ((__half2*)oh)[i * 2 + 1] = __halves2half2(__float2half_rn(v.z), __float2half_rn(v.w));
}

// ---------------- transpose fp32 [R][C] -> fp16 hi/lo [C][R], with scale ----------------
__global__ void transp_split(const float* __restrict__ in, int ild,
                             __half* __restrict__ oh, __half* __restrict__ ol,
                             int old_, float scale)
{
    __shared__ float t[32][33];
    int r0 = blockIdx.y * 32, c0 = blockIdx.x * 32;
    int tx = threadIdx.x, ty = threadIdx.y;
#pragma unroll
    for (int i = 0; i < 32; i += 8) t[ty + i][tx] = in[(size_t)(r0 + ty + i) * ild + c0 + tx] * scale;
    __syncthreads();
#pragma unroll
    for (int i = 0; i < 32; i += 8) {
        float v = t[tx][ty + i];
        __half hh = __float2half_rn(v);
        size_t o = (size_t)(c0 + ty + i) * old_ + r0 + tx;
        oh[o] = hh;
        ol[o] = __float2half_rn(v - __half2float(hh));
    }
}

// ---------------- fused attention weight transpose: Wq(x0.125), Wk, Wv, Wo ----------------
__global__ void transp_w4(const float* __restrict__ Wq, const float* __restrict__ Wk,
                          const float* __restrict__ Wv, const float* __restrict__ Wo,
                          __half* __restrict__ qkv_h, __half* __restrict__ qkv_l,
                          __half* __restrict__ wo_h,  __half* __restrict__ wo_l)
{
    __shared__ float t[32][33];
    int z = blockIdx.z;
    const float* in = (z == 0) ? Wq : (z == 1) ? Wk : (z == 2) ? Wv : Wo;
    float scale = (z == 0) ? 0.125f : 1.0f;
    __half* oh = (z < 3) ? qkv_h + (size_t)z * D_MODEL * D_MODEL : wo_h;
    __half* ol = (z < 3) ? qkv_l + (size_t)z * D_MODEL * D_MODEL : wo_l;
    int r0 = blockIdx.y * 32, c0 = blockIdx.x * 32;
    int tx = threadIdx.x, ty = threadIdx.y;
#pragma unroll
    for (int i = 0; i < 32; i += 8) t[ty + i][tx] = in[(size_t)(r0 + ty + i) * D_MODEL + c0 + tx] * scale;
    __syncthreads();
#pragma unroll
    for (int i = 0; i < 32; i += 8) {
        float v = t[tx][ty + i];
        __half hh = __float2half_rn(v);
        size_t o = (size_t)(c0 + ty + i) * D_MODEL + r0 + tx;
        oh[o] = hh;
        ol[o] = __float2half_rn(v - __half2float(hh));
    }
}

// ---------------- per-head V transpose from split-fp16 QKV ----------------
__global__ void transp_v(const __half* __restrict__ ih, const __half* __restrict__ il,
                         __half* __restrict__ oh, __half* __restrict__ ol)
{
    __shared__ __half th[32][33], tl[32][33];
    int z = blockIdx.z, b = z >> 4, h = z & 15;
    const size_t ib = (size_t)b * SEQ * QKV3 + 2048 + (size_t)h * DK;
    const size_t ob = (size_t)z * DK * SEQ;
    int r0 = blockIdx.y * 32, c0 = blockIdx.x * 32;
    int tx = threadIdx.x, ty = threadIdx.y;
#pragma unroll
    for (int i = 0; i < 32; i += 8) {
        size_t o = ib + (size_t)(r0 + ty + i) * QKV3 + c0 + tx;
        th[ty + i][tx] = ih[o];
        tl[ty + i][tx] = il[o];
    }
    __syncthreads();
#pragma unroll
    for (int i = 0; i < 32; i += 8) {
        size_t o = ob + (size_t)(c0 + ty + i) * SEQ + r0 + tx;
        oh[o] = th[tx][ty + i];
        ol[o] = tl[tx][ty + i];
    }
}

// ---------------- out = LayerNorm(X + Y), optional fp16 hi output ----------------
template<int SPLIT>
__global__ void __launch_bounds__(256) add_ln_kernel(const float* __restrict__ X,
                                                     const float* __restrict__ Y,
                                                     const float* __restrict__ gamma,
                                                     const float* __restrict__ beta,
                                                     float* __restrict__ out,
                                                     __half* __restrict__ oh)
{
    const int row = blockIdx.x;
    const int tid = threadIdx.x;
    const int lane = tid & 31, wid = tid >> 5;
    __shared__ float red[8];

    const float* xr = X + (size_t)row * D_MODEL;
    const float* yr = Y + (size_t)row * D_MODEL;
    float4 xv = *(const float4*)(xr + tid * 4);
    float4 yv = *(const float4*)(yr + tid * 4);
    float v0 = xv.x + yv.x, v1 = xv.y + yv.y, v2 = xv.z + yv.z, v3 = xv.w + yv.w;

    float s = v0 + v1 + v2 + v3;
#pragma unroll
    for (int o = 16; o > 0; o >>= 1) s += __shfl_xor_sync(0xffffffffu, s, o);
    if (lane == 0) red[wid] = s;
    __syncthreads();
    float tot = 0.f;
#pragma unroll
    for (int w = 0; w < 8; w++) tot += red[w];
    float mu = tot * (1.0f / D_MODEL);
    __syncthreads();

    float d0 = v0 - mu, d1 = v1 - mu, d2 = v2 - mu, d3 = v3 - mu;
    float sq = d0 * d0 + d1 * d1 + d2 * d2 + d3 * d3;
#pragma unroll
    for (int o = 16; o > 0; o >>= 1) sq += __shfl_xor_sync(0xffffffffu, sq, o);
    if (lane == 0) red[wid] = sq;
    __syncthreads();
    float vtot = 0.f;
#pragma unroll
    for (int w = 0; w < 8; w++) vtot += red[w];
    float inv = rsqrtf(vtot * (1.0f / D_MODEL) + EPS);

    float4 gv = *(const float4*)(gamma + tid * 4);
    float4 bv = *(const float4*)(beta + tid * 4);
    float o0 = d0 * inv * gv.x + bv.x;
    float o1 = d1 * inv * gv.y + bv.y;
    float o2 = d2 * inv * gv.z + bv.z;
    float o3 = d3 * inv * gv.w + bv.w;
    float4 o4; o4.x = o0; o4.y = o1; o4.z = o2; o4.w = o3;
    *(float4*)(out + (size_t)row * D_MODEL + tid * 4) = o4;
    if (SPLIT) {
        size_t base = (size_t)row * D_MODEL + tid * 4;
        ((__half2*)(oh + base))[0] = __halves2half2(__float2half_rn(o0), __float2half_rn(o1));
        ((__half2*)(oh + base))[1] = __halves2half2(__float2half_rn(o2), __float2half_rn(o3));
    }
}

// ---------------- host ----------------
#define GETP(var, sym) void* var; cudaGetSymbolAddress(&var, sym)
#define HF(p) ((__half*)(p))

extern "C" void kernel_launch(void* const* d_in, const int* in_sizes, int n_in,
                              void* d_out, int out_size)
{
    const float* x   = (const float*)d_in[0];
    const int*   msk = (const int*)  d_in[1];
    const float* Wq  = (const float*)d_in[2];
    const float* bq  = (const float*)d_in[3];
    const float* Wk  = (const float*)d_in[4];
    const float* bk  = (const float*)d_in[5];
    const float* Wv  = (const float*)d_in[6];
    const float* bv  = (const float*)d_in[7];
    const float* Wo  = (const float*)d_in[8];
    const float* bo  = (const float*)d_in[9];
    const float* g1  = (const float*)d_in[10];
    const float* be1 = (const float*)d_in[11];
    const float* W1  = (const float*)d_in[12];
    const float* b1  = (const float*)d_in[13];
    const float* W2  = (const float*)d_in[14];
    const float* b2  = (const float*)d_in[15];
    const float* g2  = (const float*)d_in[16];
    const float* be2 = (const float*)d_in[17];
    float* out = (float*)d_out;

    GETP(pT, g_t);      GETP(pH, g_h);     GETP(pAf, g_attn_f32);
    GETP(pSt, g_stats); GETP(pMS, g_MS);
    GETP(pxh, g_xc_h);
    GETP(pWh, g_Wqkv_h); GETP(pWl, g_Wqkv_l);
    GETP(pWoh, g_Wot_h); GETP(pWol, g_Wot_l);
    GETP(pW1h, g_W1t_h); GETP(pW1l, g_W1t_l);
    GETP(pW2h, g_W2t_h); GETP(pW2l, g_W2t_l);
    GETP(pQKVh, g_qkv_h); GETP(pQKVl, g_qkv_l);
    GETP(pVth, g_Vt_h); GETP(pVtl, g_Vt_l);
    GETP(pCh, g_ctx_h);
    GETP(pHh, g_hc_h);
    GETP(pFh, g_ff_h);

    const size_t OUT_ELEMS  = (size_t)ROWS * D_MODEL;
    const size_t ATTN_ELEMS = (size_t)HZ * SEQ * SEQ;
    float* attn = ((size_t)out_size >= OUT_ELEMS + ATTN_ELEMS) ? out + OUT_ELEMS : (float*)pAf;

    const int SMG  = 3 * (128 * 80 + 2 * 64 * 80);            // 61440
    const int SMCTX = 2 * (128 * 80) + 3 * (2 * 64 * 80);     // 51200
    cudaFuncSetAttribute(gemm_mm<5,0,0,0>, cudaFuncAttributeMaxDynamicSharedMemorySize, SMG);
    cudaFuncSetAttribute(gemm_mm<3,1,1,0>, cudaFuncAttributeMaxDynamicSharedMemorySize, SMG);
    cudaFuncSetAttribute(gemm_mm<0,0,0,0>, cudaFuncAttributeMaxDynamicSharedMemorySize, SMG);
    cudaFuncSetAttribute(gemm_mm<2,0,0,0>, cudaFuncAttributeMaxDynamicSharedMemorySize, SMG);
    cudaFuncSetAttribute(ctx_mm,           cudaFuncAttributeMaxDynamicSharedMemorySize, SMCTX);

    dim3 blk(256);
    dim3 tblk(32, 8);

    // 0: x -> fp16 hi
    conv_h<<<ROWS * D_MODEL / 4 / 256, blk>>>(x, HF(pxh), ROWS * D_MODEL / 4);
    // 1: attention weights fused transpose (Wq x0.125, Wk, Wv, Wo)
    transp_w4<<<dim3(32, 32, 4), tblk>>>(Wq, Wk, Wv, Wo, HF(pWh), HF(pWl), HF(pWoh), HF(pWol));
    // 2: fused QKV GEMM
    gemm_mm<5,0,0,0><<<dim3(QKV3 / 64, 32, 1), blk, SMG>>>(
        HF(pxh), D_MODEL, 0, HF(pWh), HF(pWl), D_MODEL, 0,
        nullptr, HF(pQKVh), HF(pQKVl), 0, QKV3, bq, bk, bv, nullptr, nullptr, D_MODEL);
    // 3: scores GEMM + per-tile stats (restructured epilogue)
    gemm_mm<3,1,1,0><<<dim3(32, 16, HZ), blk, SMG>>>(
        HF(pQKVh), QKV3, 0, HF(pQKVh), HF(pQKVl), QKV3, 1024,
        attn, nullptr, nullptr, (long long)SEQ * SEQ, SEQ,
        nullptr, nullptr, nullptr, msk, (float2*)pSt, DK);
    // 4: merge stats
    merge_stats<<<HZ * SEQ / 256, blk>>>((const float2*)pSt, (float2*)pMS);
    // 5: V per-head transpose
    transp_v<<<dim3(2, 64, HZ), tblk>>>(HF(pQKVh), HF(pQKVl), HF(pVth), HF(pVtl));
    // 6: ctx (softmax fused, M=128)
    ctx_mm<<<dim3(1, 16, HZ), blk, SMCTX>>>(attn, (const float2*)pMS,
                                            HF(pVth), HF(pVtl), HF(pCh));
    // 7: O-proj, 8: LN1
    gemm_mm<0,0,0,0><<<dim3(16, 32, 1), blk, SMG>>>(
        HF(pCh), D_MODEL, 0, HF(pWoh), HF(pWol), D_MODEL, 0,
        (float*)pT, nullptr, nullptr, 0, D_MODEL, bo, nullptr, nullptr, nullptr, nullptr, D_MODEL);
    add_ln_kernel<1><<<ROWS, blk>>>(x, (const float*)pT, g1, be1, (float*)pH, HF(pHh));
    // 9-10: FFN weights
    transp_split<<<dim3(128, 32), tblk>>>(W1, DFF,     HF(pW1h), HF(pW1l), D_MODEL, 1.0f);
    transp_split<<<dim3(32, 128), tblk>>>(W2, D_MODEL, HF(pW2h), HF(pW2l), DFF, 1.0f);
    // 11: FF1, 12: FF2, 13: LN2
    gemm_mm<2,0,0,0><<<dim3(64, 32, 1), blk, SMG>>>(
        HF(pHh), D_MODEL, 0, HF(pW1h), HF(pW1l), D_MODEL, 0,
        nullptr, HF(pFh), nullptr, 0, DFF, b1, nullptr, nullptr, nullptr, nullptr, D_MODEL);
    gemm_mm<0,0,0,0><<<dim3(16, 32, 1), blk, SMG>>>(
        HF(pFh), DFF, 0, HF(pW2h), HF(pW2l), DFF, 0,
        (float*)pT, nullptr, nullptr, 0, D_MODEL, b2, nullptr, nullptr, nullptr, nullptr, DFF);
    add_ln_kernel<0><<<ROWS, blk>>>((const float*)pH, (const float*)pT, g2, be2, out, nullptr);
}